// round 9
// baseline (speedup 1.0000x reference)
#include <cuda_runtime.h>
#include <cuda_bf16.h>

#define BATCH 8
#define CH    128
#define HH    112
#define WW    112
#define HWSZ  12544     // 112*112
#define NH    4
#define HD    32
#define KS    7
#define KK2   49
#define SCALE 0.17677669529663687f   // 32^-0.5

// Persistent scratch (static device allocations).
static __device__ __align__(16) __nv_bfloat16 g_wqh[3*CH*CH];        // qkv_w hi, [n][k]
static __device__ __align__(16) __nv_bfloat16 g_wql[3*CH*CH];
static __device__ __align__(16) __nv_bfloat16 g_pwh[CH*CH];          // proj_w hi
static __device__ __align__(16) __nv_bfloat16 g_pwl[CH*CH];
static __device__ __align__(16) float g_v  [BATCH*NH*HWSZ*HD];       // (b,h,p,d)
static __device__ __align__(16) float g_dot[BATCH*NH*HWSZ];          // (b,h,p)
static __device__ __align__(16) __nv_bfloat16 g_ath[BATCH*HWSZ*CH];  // att hi, (b,p,c)
static __device__ __align__(16) __nv_bfloat16 g_atl[BATCH*HWSZ*CH];  // att lo

// ---------------- helpers ----------------------------------------

__device__ __forceinline__ unsigned bfpack(__nv_bfloat16 a, __nv_bfloat16 b) {
    return (unsigned)__bfloat16_as_ushort(a) | ((unsigned)__bfloat16_as_ushort(b) << 16);
}

__device__ __forceinline__ void split4(float4 v, uint2& hi, uint2& lo) {
    __nv_bfloat16 hx = __float2bfloat16(v.x);
    __nv_bfloat16 hy = __float2bfloat16(v.y);
    __nv_bfloat16 hz = __float2bfloat16(v.z);
    __nv_bfloat16 hw = __float2bfloat16(v.w);
    __nv_bfloat16 lx = __float2bfloat16(v.x - __bfloat162float(hx));
    __nv_bfloat16 ly = __float2bfloat16(v.y - __bfloat162float(hy));
    __nv_bfloat16 lz = __float2bfloat16(v.z - __bfloat162float(hz));
    __nv_bfloat16 lw = __float2bfloat16(v.w - __bfloat162float(hw));
    hi.x = bfpack(hx, hy); hi.y = bfpack(hz, hw);
    lo.x = bfpack(lx, ly); lo.y = bfpack(lz, lw);
}

__device__ __forceinline__ void ldsm4(unsigned* r, unsigned addr) {
    asm volatile("ldmatrix.sync.aligned.m8n8.x4.shared.b16 {%0,%1,%2,%3}, [%4];"
                 : "=r"(r[0]), "=r"(r[1]), "=r"(r[2]), "=r"(r[3]) : "r"(addr));
}
__device__ __forceinline__ void ldsm4t(unsigned* r, unsigned addr) {
    asm volatile("ldmatrix.sync.aligned.m8n8.x4.trans.shared.b16 {%0,%1,%2,%3}, [%4];"
                 : "=r"(r[0]), "=r"(r[1]), "=r"(r[2]), "=r"(r[3]) : "r"(addr));
}
__device__ __forceinline__ void mma16816(float* c, const unsigned* a, const unsigned* b) {
    asm volatile(
        "mma.sync.aligned.m16n8k16.row.col.f32.bf16.bf16.f32 "
        "{%0,%1,%2,%3}, {%4,%5,%6,%7}, {%8,%9}, {%0,%1,%2,%3};"
        : "+f"(c[0]), "+f"(c[1]), "+f"(c[2]), "+f"(c[3])
        : "r"(a[0]), "r"(a[1]), "r"(a[2]), "r"(a[3]), "r"(b[0]), "r"(b[1]));
}

__device__ __forceinline__ void cpa16(unsigned dst, const void* src) {
    asm volatile("cp.async.cg.shared.global [%0], [%1], 16;" :: "r"(dst), "l"(src));
}
__device__ __forceinline__ void cpcommit() {
    asm volatile("cp.async.commit_group;");
}
__device__ __forceinline__ void cpwait1() {
    asm volatile("cp.async.wait_group 1;");
}
__device__ __forceinline__ void cpwait0() {
    asm volatile("cp.async.wait_group 0;");
}

// ------------------------------------------------------------------
// Pre-split kernel: weights fp32 -> bf16 hi/lo (tiny)
// ------------------------------------------------------------------
__global__ __launch_bounds__(256) void split_w_kernel(
    const float* __restrict__ qw, const float* __restrict__ pw)
{
    int i = (blockIdx.x * 256 + threadIdx.x) * 4;
    uint2 hi, lo;
    if (i < 3 * CH * CH) {
        float4 v = *(const float4*)&qw[i];
        split4(v, hi, lo);
        *(uint2*)&g_wqh[i] = hi;
        *(uint2*)&g_wql[i] = lo;
    } else {
        int j = i - 3 * CH * CH;
        float4 v = *(const float4*)&pw[j];
        split4(v, hi, lo);
        *(uint2*)&g_pwh[j] = hi;
        *(uint2*)&g_pwl[j] = lo;
    }
}

// ------------------------------------------------------------------
// Kernel 1: fused QKV GEMM + q.k dot. bf16 3-term split.
// M-tile 64 px, 256 threads (8 warps, 2m x 4n of 32x32) -> 96KB smem,
// 2 CTA/SM: cross-CTA overlap hides barriers/epilogues.
// A (x tile, [128k][64m], 144B rows hi/lo) split in prologue;
// B (pre-split weights) streamed via cp.async 3-buffer ring.
// ------------------------------------------------------------------
#define QA_H 0
#define QA_LO 18432
#define QB0  36864
#define QBUF 20480
#define QSM  98304

__device__ __forceinline__ void qkv_issueB(unsigned sb, int t, int it)
{
    const int nt = it >> 2, kt = it & 3, buf = it % 3;
    const int nrow = t >> 1, half = t & 1;
    unsigned bd = sb + QB0 + buf * QBUF + nrow * 80 + half * 32;
    size_t off = (size_t)(nt * 128 + nrow) * CH + kt * 32 + half * 16;
    cpa16(bd,              g_wqh + off);
    cpa16(bd + 16,         g_wqh + off + 8);
    cpa16(bd + 10240,      g_wql + off);
    cpa16(bd + 10240 + 16, g_wql + off + 8);
}

__global__ __launch_bounds__(256, 2) void qkvdot_kernel(
    const float* __restrict__ x, const float* __restrict__ bias)
{
    extern __shared__ __align__(16) char sm[];
    const unsigned sb = (unsigned)__cvta_generic_to_shared(sm);

    const int mtile = blockIdx.x;            // 0..1567
    const int b     = mtile / 196;           // 12544/64 = 196
    const int hw0   = (mtile - b * 196) * 64;
    const int t     = threadIdx.x;
    const int l     = t & 31, w = t >> 5;
    const int wm    = w >> 2, wn = w & 3;    // 2m x 4n warp grid
    const int g     = l >> 3, i = l & 7;

    // ---- prologue: B(0), B(1) via cp.async; A fp32 load + split ----
    {
        qkv_issueB(sb, t, 0);
        cpcommit();
        qkv_issueB(sb, t, 1);
        cpcommit();

        const float* xb = x + (size_t)b * (CH * HWSZ) + hw0;
        const int m4 = (t & 15) * 4;         // 0..60
        const int kr = t >> 4;               // 0..15
        float4 av[8];
#pragma unroll
        for (int j = 0; j < 8; ++j)
            av[j] = *(const float4*)(xb + (size_t)(kr + j * 16) * HWSZ + m4);
#pragma unroll
        for (int j = 0; j < 8; ++j) {
            uint2 hi, lo;
            split4(av[j], hi, lo);
            unsigned ad = sb + QA_H + (kr + j * 16) * 144 + m4 * 2;
            *(uint2*)__cvta_shared_to_generic(ad) = hi;
            *(uint2*)__cvta_shared_to_generic(ad + QA_LO) = lo;
        }
        cpwait1();
        __syncthreads();
    }

    float c[2][4][4];
    float qreg[2][4][4];
#pragma unroll
    for (int mf = 0; mf < 2; ++mf)
#pragma unroll
        for (int nf = 0; nf < 4; ++nf)
#pragma unroll
            for (int r2 = 0; r2 < 4; ++r2) c[mf][nf][r2] = 0.f;

    for (int it = 0; it < 12; ++it) {
        const int nt = it >> 2, kt = it & 3, buf = it % 3;

        if (it < 10) { qkv_issueB(sb, t, it + 2); cpcommit(); }

        const unsigned Bb = sb + QB0 + buf * QBUF;
#pragma unroll
        for (int kb = 0; kb < 32; kb += 16) {
            unsigned ah[2][4], al_[2][4], bh[4][2], bl[4][2];
#pragma unroll
            for (int mf = 0; mf < 2; ++mf) {
                int row  = kt * 32 + kb + i + ((g >> 1) << 3);
                int mcol = wm * 32 + mf * 16 + ((g & 1) << 3);
                unsigned ad = sb + QA_H + row * 144 + mcol * 2;
                ldsm4t(ah[mf], ad);
                ldsm4t(al_[mf], ad + QA_LO);
            }
#pragma unroll
            for (int ng = 0; ng < 2; ++ng) {
                int nrow = wn * 32 + ng * 16 + ((g >> 1) << 3) + i;
                unsigned bd = Bb + nrow * 80 + kb * 2 + ((g & 1) << 4);
                unsigned r[4];
                ldsm4(r, bd);
                bh[ng * 2][0] = r[0]; bh[ng * 2][1] = r[1];
                bh[ng * 2 + 1][0] = r[2]; bh[ng * 2 + 1][1] = r[3];
                ldsm4(r, bd + 10240);
                bl[ng * 2][0] = r[0]; bl[ng * 2][1] = r[1];
                bl[ng * 2 + 1][0] = r[2]; bl[ng * 2 + 1][1] = r[3];
            }
#pragma unroll
            for (int mf = 0; mf < 2; ++mf)
#pragma unroll
                for (int nf = 0; nf < 4; ++nf) {
                    mma16816(c[mf][nf], ah[mf], bh[nf]);
                    mma16816(c[mf][nf], ah[mf], bl[nf]);
                    mma16816(c[mf][nf], al_[mf], bh[nf]);
                }
        }

        if (kt == 3) {
            if (nt == 0) {
#pragma unroll
                for (int mf = 0; mf < 2; ++mf)
#pragma unroll
                    for (int nf = 0; nf < 4; ++nf) {
                        int n = wn * 32 + nf * 8 + (l & 3) * 2;
                        float b0 = bias[n], b1 = bias[n + 1];
                        qreg[mf][nf][0] = c[mf][nf][0] + b0;
                        qreg[mf][nf][1] = c[mf][nf][1] + b1;
                        qreg[mf][nf][2] = c[mf][nf][2] + b0;
                        qreg[mf][nf][3] = c[mf][nf][3] + b1;
                    }
            } else if (nt == 1) {
#pragma unroll
                for (int mf = 0; mf < 2; ++mf) {
                    float s0 = 0.f, s1 = 0.f;
                    int m = wm * 32 + mf * 16 + (l >> 2);
#pragma unroll
                    for (int nf = 0; nf < 4; ++nf) {
                        int n = wn * 32 + nf * 8 + (l & 3) * 2;
                        float b0 = bias[128 + n], b1 = bias[128 + n + 1];
                        s0 += qreg[mf][nf][0] * (c[mf][nf][0] + b0)
                            + qreg[mf][nf][1] * (c[mf][nf][1] + b1);
                        s1 += qreg[mf][nf][2] * (c[mf][nf][2] + b0)
                            + qreg[mf][nf][3] * (c[mf][nf][3] + b1);
                    }
                    s0 += __shfl_xor_sync(0xffffffffu, s0, 1);
                    s0 += __shfl_xor_sync(0xffffffffu, s0, 2);
                    s1 += __shfl_xor_sync(0xffffffffu, s1, 1);
                    s1 += __shfl_xor_sync(0xffffffffu, s1, 2);
                    if ((l & 3) == 0) {
                        size_t base = (size_t)(b * NH + wn) * HWSZ + hw0;
                        g_dot[base + m]     = s0 * SCALE;
                        g_dot[base + m + 8] = s1 * SCALE;
                    }
                }
            } else {
#pragma unroll
                for (int mf = 0; mf < 2; ++mf)
#pragma unroll
                    for (int nf = 0; nf < 4; ++nf) {
                        int n = wn * 32 + nf * 8 + (l & 3) * 2;
                        int m = wm * 32 + mf * 16 + (l >> 2);
                        float b0 = bias[256 + n], b1 = bias[256 + n + 1];
                        int d = n & 31;
                        float* hb = g_v + ((size_t)(b * NH + wn) * HWSZ + hw0) * HD + d;
                        *(float2*)&hb[(size_t)m * HD] =
                            make_float2(c[mf][nf][0] + b0, c[mf][nf][1] + b1);
                        *(float2*)&hb[(size_t)(m + 8) * HD] =
                            make_float2(c[mf][nf][2] + b0, c[mf][nf][3] + b1);
                    }
            }
#pragma unroll
            for (int mf = 0; mf < 2; ++mf)
#pragma unroll
                for (int nf = 0; nf < 4; ++nf)
#pragma unroll
                    for (int r2 = 0; r2 < 4; ++r2) c[mf][nf][r2] = 0.f;
        }

        if (it < 10)       cpwait1();
        else if (it == 10) cpwait0();
        __syncthreads();
    }
}

// ------------------------------------------------------------------
// Kernel 2: neighborhood attention (circular). Byte-identical to R8.
// ------------------------------------------------------------------
#define A_DS  0
#define A_RS  2112
#define A_VS  2368
#define VSTR  44
#define ASM   (A_VS + 484 * VSTR * 4)   // 87552

__global__ __launch_bounds__(256) void attn_kernel(const float* __restrict__ rpb)
{
    extern __shared__ __align__(16) char asm_[];
    float* ds = (float*)(asm_ + A_DS);      // [22*24]
    float* rs = (float*)(asm_ + A_RS);      // [49]
    float* vs = (float*)(asm_ + A_VS);      // [484][44] two 16-ch slabs

    const int bh = blockIdx.z;        // b*4 + h
    const int h  = bh & 3;
    const int b  = bh >> 2;
    const int y0 = blockIdx.y * 16;
    const int x0 = blockIdx.x * 16;
    const int tid = threadIdx.x;

    for (int idx = tid; idx < 484; idx += 256) {
        int r  = idx / 22, cc = idx - r * 22;
        int gy = y0 + r;  if (gy >= HH) gy -= HH;
        int gx = x0 + cc; if (gx >= WW) gx -= WW;
        ds[r * 24 + cc] = g_dot[(size_t)bh * HWSZ + gy * WW + gx];
    }
    if (tid < KK2) rs[tid] = rpb[h * KK2 + tid];

    const float* vbase = g_v + (size_t)bh * (HWSZ * HD);

    for (int idx = tid; idx < 484 * 8; idx += 256) {
        int pix = idx >> 3, gg = idx & 7;
        int r  = pix / 22, cc = pix - r * 22;
        int gy = y0 + r;  if (gy >= HH) gy -= HH;
        int gx = x0 + cc; if (gx >= WW) gx -= WW;
        int soff = pix * VSTR + gg * 4 + ((gg >= 4) ? 4 : 0);
        *(float4*)&vs[soff] =
            *(const float4*)&vbase[(size_t)(gy * WW + gx) * HD + gg * 4];
    }
    __syncthreads();

    const int ty = tid >> 4, tx = tid & 15;

    float wgt[KK2];
    float mx = -1e30f;
#pragma unroll
    for (int i = 0; i < 7; ++i)
#pragma unroll
        for (int j = 0; j < 7; ++j) {
            float val = ds[(ty + i) * 24 + tx + j] + rs[i * 7 + j];
            wgt[i * 7 + j] = val;
            mx = fmaxf(mx, val);
        }
    float sum = 0.f;
#pragma unroll
    for (int n = 0; n < KK2; ++n) { wgt[n] = __expf(wgt[n] - mx); sum += wgt[n]; }
    const float inv = 1.f / sum;

    const int p = (y0 + ty) * WW + (x0 + tx);
    const size_t obase = (size_t)(b * HWSZ + p) * CH + h * HD;

#pragma unroll
    for (int half = 0; half < 2; ++half) {
        const int vo = half * 20;
        float4 acc[4];
#pragma unroll
        for (int gg = 0; gg < 4; ++gg) acc[gg] = make_float4(0.f, 0.f, 0.f, 0.f);
#pragma unroll
        for (int i = 0; i < 7; ++i)
#pragma unroll
            for (int j = 0; j < 7; ++j) {
                float wt  = wgt[i * 7 + j];
                int   pix = (ty + i) * 22 + (tx + j);
#pragma unroll
                for (int gg = 0; gg < 4; ++gg) {
                    float4 vv = *(const float4*)&vs[pix * VSTR + vo + gg * 4];
                    acc[gg].x = fmaf(wt, vv.x, acc[gg].x);
                    acc[gg].y = fmaf(wt, vv.y, acc[gg].y);
                    acc[gg].z = fmaf(wt, vv.z, acc[gg].z);
                    acc[gg].w = fmaf(wt, vv.w, acc[gg].w);
                }
            }
        unsigned hi_u[8], lo_u[8];
#pragma unroll
        for (int gg = 0; gg < 4; ++gg) {
            float f[4] = { acc[gg].x * inv, acc[gg].y * inv,
                           acc[gg].z * inv, acc[gg].w * inv };
#pragma unroll
            for (int e = 0; e < 2; ++e) {
                float f0 = f[e * 2], f1 = f[e * 2 + 1];
                __nv_bfloat16 h0 = __float2bfloat16(f0);
                __nv_bfloat16 h1 = __float2bfloat16(f1);
                __nv_bfloat16 l0 = __float2bfloat16(f0 - __bfloat162float(h0));
                __nv_bfloat16 l1 = __float2bfloat16(f1 - __bfloat162float(h1));
                hi_u[gg * 2 + e] = bfpack(h0, h1);
                lo_u[gg * 2 + e] = bfpack(l0, l1);
            }
        }
        size_t ob = obase + half * 16;
        *(uint4*)&g_ath[ob]     = make_uint4(hi_u[0], hi_u[1], hi_u[2], hi_u[3]);
        *(uint4*)&g_ath[ob + 8] = make_uint4(hi_u[4], hi_u[5], hi_u[6], hi_u[7]);
        *(uint4*)&g_atl[ob]     = make_uint4(lo_u[0], lo_u[1], lo_u[2], lo_u[3]);
        *(uint4*)&g_atl[ob + 8] = make_uint4(lo_u[4], lo_u[5], lo_u[6], lo_u[7]);
    }
}

// ------------------------------------------------------------------
// Kernel 3: proj GEMM + transpose. M-tile 64, 256 threads, 98KB smem
// -> 2 CTA/SM. B (weights hi/lo, 272B rows) resident;
// A (att hi/lo, 80B rows) streamed per kt via cp.async ring.
// ------------------------------------------------------------------
#define PB_H 0
#define PB_L 34816
#define PA0  69632
#define PBUF 10240
#define PSM  100352

__device__ __forceinline__ void proj_issueA(unsigned sb, int t, int m0, int kt)
{
    const int buf = kt % 3;
    const int mrow = t >> 2, c4 = t & 3;
    unsigned ad = sb + PA0 + buf * PBUF + mrow * 80 + c4 * 16;
    size_t off = (size_t)(m0 + mrow) * CH + kt * 32 + c4 * 8;
    cpa16(ad,        g_ath + off);
    cpa16(ad + 5120, g_atl + off);
}

__global__ __launch_bounds__(256, 2) void proj_kernel(
    const float* __restrict__ pb, float* __restrict__ out)
{
    extern __shared__ __align__(16) char sm[];
    const unsigned sb = (unsigned)__cvta_generic_to_shared(sm);

    const int mtile = blockIdx.x;            // 0..1567
    const int m0    = mtile * 64;
    const int t     = threadIdx.x;
    const int l     = t & 31, w = t >> 5;
    const int wm    = w >> 2, wn = w & 3;
    const int g     = l >> 3, i = l & 7;

    {
#pragma unroll
        for (int j = 0; j < 8; ++j) {
            int cid = t + j * 256;
            int row = cid >> 4, c16 = cid & 15;
            cpa16(sb + PB_H + row * 272 + c16 * 16, g_pwh + (size_t)row * CH + c16 * 8);
            cpa16(sb + PB_L + row * 272 + c16 * 16, g_pwl + (size_t)row * CH + c16 * 8);
        }
        proj_issueA(sb, t, m0, 0);
        cpcommit();
        proj_issueA(sb, t, m0, 1);
        cpcommit();
        cpwait1();
        __syncthreads();
    }

    float c[2][4][4];
#pragma unroll
    for (int mf = 0; mf < 2; ++mf)
#pragma unroll
        for (int nf = 0; nf < 4; ++nf)
#pragma unroll
            for (int r2 = 0; r2 < 4; ++r2) c[mf][nf][r2] = 0.f;

    for (int kt = 0; kt < 4; ++kt) {
        const int buf = kt % 3;
        if (kt < 2) { proj_issueA(sb, t, m0, kt + 2); cpcommit(); }

        const unsigned Ab = sb + PA0 + buf * PBUF;
#pragma unroll
        for (int kb = 0; kb < 32; kb += 16) {
            unsigned ah[2][4], al_[2][4], bh[4][2], bl[4][2];
#pragma unroll
            for (int mf = 0; mf < 2; ++mf) {
                int mrow = wm * 32 + mf * 16 + ((g & 1) << 3) + i;
                unsigned ad = Ab + mrow * 80 + kb * 2 + ((g >> 1) << 4);
                ldsm4(ah[mf], ad);
                ldsm4(al_[mf], ad + 5120);
            }
#pragma unroll
            for (int ng = 0; ng < 2; ++ng) {
                int nrow = wn * 32 + ng * 16 + ((g >> 1) << 3) + i;
                unsigned bd = sb + PB_H + nrow * 272 + (kt * 32 + kb) * 2 + ((g & 1) << 4);
                unsigned r[4];
                ldsm4(r, bd);
                bh[ng * 2][0] = r[0]; bh[ng * 2][1] = r[1];
                bh[ng * 2 + 1][0] = r[2]; bh[ng * 2 + 1][1] = r[3];
                ldsm4(r, bd + (PB_L - PB_H));
                bl[ng * 2][0] = r[0]; bl[ng * 2][1] = r[1];
                bl[ng * 2 + 1][0] = r[2]; bl[ng * 2 + 1][1] = r[3];
            }
#pragma unroll
            for (int mf = 0; mf < 2; ++mf)
#pragma unroll
                for (int nf = 0; nf < 4; ++nf) {
                    mma16816(c[mf][nf], ah[mf], bh[nf]);
                    mma16816(c[mf][nf], ah[mf], bl[nf]);
                    mma16816(c[mf][nf], al_[mf], bh[nf]);
                }
        }
        if (kt < 2)       cpwait1();
        else if (kt == 2) cpwait0();
        __syncthreads();
    }

    // ---- epilogue: smem transpose, 4 chunks of 32 channels ----
    const int b   = mtile / 196;
    const int hw0 = (mtile - b * 196) * 64;
    float* eb = (float*)(sm + PA0);   // [32][68], reuses A ring

    for (int nc = 0; nc < 4; ++nc) {
        if (wn == nc) {
#pragma unroll
            for (int mf = 0; mf < 2; ++mf)
#pragma unroll
                for (int nf = 0; nf < 4; ++nf) {
                    int nl = nf * 8 + (l & 3) * 2;
                    int m  = wm * 32 + mf * 16 + (l >> 2);
                    eb[nl * 68 + m]           = c[mf][nf][0];
                    eb[(nl + 1) * 68 + m]     = c[mf][nf][1];
                    eb[nl * 68 + m + 8]       = c[mf][nf][2];
                    eb[(nl + 1) * 68 + m + 8] = c[mf][nf][3];
                }
        }
        __syncthreads();
        {
            int nl = t >> 3;              // 0..31
            int mm = (t & 7) * 8;         // 0..56
            int ng2 = nc * 32 + nl;
            float bias = pb[ng2];
            float* orow = out + (size_t)(b * CH + ng2) * HWSZ + hw0;
#pragma unroll
            for (int j = 0; j < 2; ++j) {
                float4 v = *(float4*)&eb[nl * 68 + mm + j * 4];
                v.x += bias; v.y += bias; v.z += bias; v.w += bias;
                *(float4*)&orow[mm + j * 4] = v;
            }
        }
        __syncthreads();
    }
}

// ------------------------------------------------------------------
extern "C" void kernel_launch(void* const* d_in, const int* in_sizes, int n_in,
                              void* d_out, int out_size)
{
    const float* x      = (const float*)d_in[0];
    const float* qkv_w  = (const float*)d_in[1];
    const float* qkv_b  = (const float*)d_in[2];
    const float* rpb    = (const float*)d_in[3];
    const float* proj_w = (const float*)d_in[4];
    const float* proj_b = (const float*)d_in[5];
    float* out = (float*)d_out;

    cudaFuncSetAttribute(qkvdot_kernel,
                         cudaFuncAttributeMaxDynamicSharedMemorySize, QSM);
    cudaFuncSetAttribute(attn_kernel,
                         cudaFuncAttributeMaxDynamicSharedMemorySize, ASM);
    cudaFuncSetAttribute(proj_kernel,
                         cudaFuncAttributeMaxDynamicSharedMemorySize, PSM);

    split_w_kernel<<<(3 * CH * CH + CH * CH) / 1024, 256>>>(qkv_w, proj_w);
    qkvdot_kernel<<<1568, 256, QSM>>>(x, qkv_b);
    attn_kernel<<<dim3(7, 7, 32), 256, ASM>>>(rpb);
    proj_kernel<<<1568, 256, PSM>>>(proj_b, out);
}

// round 10
// speedup vs baseline: 1.4707x; 1.4707x over previous
#include <cuda_runtime.h>
#include <cuda_bf16.h>

#define BATCH 8
#define CH    128
#define HH    112
#define WW    112
#define HWSZ  12544     // 112*112
#define NH    4
#define HD    32
#define KS    7
#define KK2   49
#define SCALE 0.17677669529663687f   // 32^-0.5

// Persistent scratch (static device allocations).
static __device__ __align__(16) __nv_bfloat16 g_wqh[3*CH*CH];        // qkv_w hi, [n][k]
static __device__ __align__(16) __nv_bfloat16 g_wql[3*CH*CH];
static __device__ __align__(16) __nv_bfloat16 g_pwh[CH*CH];          // proj_w hi
static __device__ __align__(16) __nv_bfloat16 g_pwl[CH*CH];
static __device__ __align__(16) float g_v  [BATCH*NH*HWSZ*HD];       // (b,h,p,d)
static __device__ __align__(16) float g_dot[BATCH*NH*HWSZ];          // (b,h,p)
// att hi/lo in HEAD-BLOCKED layout (b,h,p,d): attn stores coalesce.
static __device__ __align__(16) __nv_bfloat16 g_ath[BATCH*NH*HWSZ*HD];
static __device__ __align__(16) __nv_bfloat16 g_atl[BATCH*NH*HWSZ*HD];

// ---------------- helpers ----------------------------------------

__device__ __forceinline__ unsigned bfpack(__nv_bfloat16 a, __nv_bfloat16 b) {
    return (unsigned)__bfloat16_as_ushort(a) | ((unsigned)__bfloat16_as_ushort(b) << 16);
}

__device__ __forceinline__ void split4(float4 v, uint2& hi, uint2& lo) {
    __nv_bfloat16 hx = __float2bfloat16(v.x);
    __nv_bfloat16 hy = __float2bfloat16(v.y);
    __nv_bfloat16 hz = __float2bfloat16(v.z);
    __nv_bfloat16 hw = __float2bfloat16(v.w);
    __nv_bfloat16 lx = __float2bfloat16(v.x - __bfloat162float(hx));
    __nv_bfloat16 ly = __float2bfloat16(v.y - __bfloat162float(hy));
    __nv_bfloat16 lz = __float2bfloat16(v.z - __bfloat162float(hz));
    __nv_bfloat16 lw = __float2bfloat16(v.w - __bfloat162float(hw));
    hi.x = bfpack(hx, hy); hi.y = bfpack(hz, hw);
    lo.x = bfpack(lx, ly); lo.y = bfpack(lz, lw);
}

__device__ __forceinline__ void ldsm4(unsigned* r, unsigned addr) {
    asm volatile("ldmatrix.sync.aligned.m8n8.x4.shared.b16 {%0,%1,%2,%3}, [%4];"
                 : "=r"(r[0]), "=r"(r[1]), "=r"(r[2]), "=r"(r[3]) : "r"(addr));
}
__device__ __forceinline__ void ldsm4t(unsigned* r, unsigned addr) {
    asm volatile("ldmatrix.sync.aligned.m8n8.x4.trans.shared.b16 {%0,%1,%2,%3}, [%4];"
                 : "=r"(r[0]), "=r"(r[1]), "=r"(r[2]), "=r"(r[3]) : "r"(addr));
}
__device__ __forceinline__ void mma16816(float* c, const unsigned* a, const unsigned* b) {
    asm volatile(
        "mma.sync.aligned.m16n8k16.row.col.f32.bf16.bf16.f32 "
        "{%0,%1,%2,%3}, {%4,%5,%6,%7}, {%8,%9}, {%0,%1,%2,%3};"
        : "+f"(c[0]), "+f"(c[1]), "+f"(c[2]), "+f"(c[3])
        : "r"(a[0]), "r"(a[1]), "r"(a[2]), "r"(a[3]), "r"(b[0]), "r"(b[1]));
}

__device__ __forceinline__ void cpa16(unsigned dst, const void* src) {
    asm volatile("cp.async.cg.shared.global [%0], [%1], 16;" :: "r"(dst), "l"(src));
}
__device__ __forceinline__ void cpcommit() {
    asm volatile("cp.async.commit_group;");
}
__device__ __forceinline__ void cpwait1() {
    asm volatile("cp.async.wait_group 1;");
}
__device__ __forceinline__ void cpwait0() {
    asm volatile("cp.async.wait_group 0;");
}

// ------------------------------------------------------------------
// Pre-split kernel: weights fp32 -> bf16 hi/lo (tiny)
// ------------------------------------------------------------------
__global__ __launch_bounds__(256) void split_w_kernel(
    const float* __restrict__ qw, const float* __restrict__ pw)
{
    int i = (blockIdx.x * 256 + threadIdx.x) * 4;
    uint2 hi, lo;
    if (i < 3 * CH * CH) {
        float4 v = *(const float4*)&qw[i];
        split4(v, hi, lo);
        *(uint2*)&g_wqh[i] = hi;
        *(uint2*)&g_wql[i] = lo;
    } else {
        int j = i - 3 * CH * CH;
        float4 v = *(const float4*)&pw[j];
        split4(v, hi, lo);
        *(uint2*)&g_pwh[j] = hi;
        *(uint2*)&g_pwl[j] = lo;
    }
}

// ------------------------------------------------------------------
// Kernel 1: fused QKV GEMM + q.k dot. bf16 3-term split.
// M-tile 128, 512 thr, 4x4 warps of 32x32.  (byte-identical to R8)
// ------------------------------------------------------------------
#define QA_H 0
#define QA_L 34816
#define QB0  69632
#define QBUF 20480
#define QSM  131072

__device__ __forceinline__ void qkv_issueB(unsigned sb, int t, int it)
{
    const int nt = it >> 2, kt = it & 3, buf = it % 3;
    const int nrow = t >> 2, c4 = t & 3;
    unsigned bd = sb + QB0 + buf * QBUF + nrow * 80 + c4 * 16;
    size_t off = (size_t)(nt * 128 + nrow) * CH + kt * 32 + c4 * 8;
    cpa16(bd,         g_wqh + off);
    cpa16(bd + 10240, g_wql + off);
}

__global__ __launch_bounds__(512) void qkvdot_kernel(
    const float* __restrict__ x, const float* __restrict__ bias)
{
    extern __shared__ __align__(16) char sm[];
    const unsigned sb = (unsigned)__cvta_generic_to_shared(sm);

    const int mtile = blockIdx.x;            // 0..783
    const int b     = mtile / 98;
    const int hw0   = (mtile - b * 98) * 128;
    const int t     = threadIdx.x;
    const int l     = t & 31, w = t >> 5;
    const int wm    = w >> 2, wn = w & 3;
    const int g     = l >> 3, i = l & 7;

    // ---- prologue: B(0), B(1) via cp.async; A fp32 load + split ----
    {
        qkv_issueB(sb, t, 0);
        cpcommit();
        qkv_issueB(sb, t, 1);
        cpcommit();

        const float* xb = x + (size_t)b * (CH * HWSZ) + hw0;
        const int m4 = (t & 31) * 4;
        const int kr = t >> 5;               // 0..15
        float4 av[8];
#pragma unroll
        for (int j = 0; j < 8; ++j)
            av[j] = *(const float4*)(xb + (size_t)(kr + j * 16) * HWSZ + m4);
#pragma unroll
        for (int j = 0; j < 8; ++j) {
            uint2 hi, lo;
            split4(av[j], hi, lo);
            unsigned ad = sb + QA_H + (kr + j * 16) * 272 + m4 * 2;
            *(uint2*)__cvta_shared_to_generic(ad) = hi;
            *(uint2*)__cvta_shared_to_generic(ad + (QA_L - QA_H)) = lo;
        }
        cpwait1();
        __syncthreads();
    }

    float c[2][4][4];
    float qreg[2][4][4];
#pragma unroll
    for (int mf = 0; mf < 2; ++mf)
#pragma unroll
        for (int nf = 0; nf < 4; ++nf)
#pragma unroll
            for (int r2 = 0; r2 < 4; ++r2) c[mf][nf][r2] = 0.f;

    for (int it = 0; it < 12; ++it) {
        const int nt = it >> 2, kt = it & 3, buf = it % 3;

        if (it < 10) { qkv_issueB(sb, t, it + 2); cpcommit(); }

        const unsigned Bb = sb + QB0 + buf * QBUF;
#pragma unroll
        for (int kb = 0; kb < 32; kb += 16) {
            unsigned ah[2][4], al_[2][4], bh[4][2], bl[4][2];
#pragma unroll
            for (int mf = 0; mf < 2; ++mf) {
                int row  = kt * 32 + kb + i + ((g >> 1) << 3);
                int mcol = wm * 32 + mf * 16 + ((g & 1) << 3);
                unsigned ad = sb + QA_H + row * 272 + mcol * 2;
                ldsm4t(ah[mf], ad);
                ldsm4t(al_[mf], ad + (QA_L - QA_H));
            }
#pragma unroll
            for (int ng = 0; ng < 2; ++ng) {
                int nrow = wn * 32 + ng * 16 + ((g >> 1) << 3) + i;
                unsigned bd = Bb + nrow * 80 + kb * 2 + ((g & 1) << 4);
                unsigned r[4];
                ldsm4(r, bd);
                bh[ng * 2][0] = r[0]; bh[ng * 2][1] = r[1];
                bh[ng * 2 + 1][0] = r[2]; bh[ng * 2 + 1][1] = r[3];
                ldsm4(r, bd + 10240);
                bl[ng * 2][0] = r[0]; bl[ng * 2][1] = r[1];
                bl[ng * 2 + 1][0] = r[2]; bl[ng * 2 + 1][1] = r[3];
            }
#pragma unroll
            for (int mf = 0; mf < 2; ++mf)
#pragma unroll
                for (int nf = 0; nf < 4; ++nf) {
                    mma16816(c[mf][nf], ah[mf], bh[nf]);
                    mma16816(c[mf][nf], ah[mf], bl[nf]);
                    mma16816(c[mf][nf], al_[mf], bh[nf]);
                }
        }

        if (kt == 3) {
            if (nt == 0) {
#pragma unroll
                for (int mf = 0; mf < 2; ++mf)
#pragma unroll
                    for (int nf = 0; nf < 4; ++nf) {
                        int n = wn * 32 + nf * 8 + (l & 3) * 2;
                        float b0 = bias[n], b1 = bias[n + 1];
                        qreg[mf][nf][0] = c[mf][nf][0] + b0;
                        qreg[mf][nf][1] = c[mf][nf][1] + b1;
                        qreg[mf][nf][2] = c[mf][nf][2] + b0;
                        qreg[mf][nf][3] = c[mf][nf][3] + b1;
                    }
            } else if (nt == 1) {
#pragma unroll
                for (int mf = 0; mf < 2; ++mf) {
                    float s0 = 0.f, s1 = 0.f;
                    int m = wm * 32 + mf * 16 + (l >> 2);
#pragma unroll
                    for (int nf = 0; nf < 4; ++nf) {
                        int n = wn * 32 + nf * 8 + (l & 3) * 2;
                        float b0 = bias[128 + n], b1 = bias[128 + n + 1];
                        s0 += qreg[mf][nf][0] * (c[mf][nf][0] + b0)
                            + qreg[mf][nf][1] * (c[mf][nf][1] + b1);
                        s1 += qreg[mf][nf][2] * (c[mf][nf][2] + b0)
                            + qreg[mf][nf][3] * (c[mf][nf][3] + b1);
                    }
                    s0 += __shfl_xor_sync(0xffffffffu, s0, 1);
                    s0 += __shfl_xor_sync(0xffffffffu, s0, 2);
                    s1 += __shfl_xor_sync(0xffffffffu, s1, 1);
                    s1 += __shfl_xor_sync(0xffffffffu, s1, 2);
                    if ((l & 3) == 0) {
                        size_t base = (size_t)(b * NH + wn) * HWSZ + hw0;
                        g_dot[base + m]     = s0 * SCALE;
                        g_dot[base + m + 8] = s1 * SCALE;
                    }
                }
            } else {
#pragma unroll
                for (int mf = 0; mf < 2; ++mf)
#pragma unroll
                    for (int nf = 0; nf < 4; ++nf) {
                        int n = wn * 32 + nf * 8 + (l & 3) * 2;
                        int m = wm * 32 + mf * 16 + (l >> 2);
                        float b0 = bias[256 + n], b1 = bias[256 + n + 1];
                        int d = n & 31;
                        float* hb = g_v + ((size_t)(b * NH + wn) * HWSZ + hw0) * HD + d;
                        *(float2*)&hb[(size_t)m * HD] =
                            make_float2(c[mf][nf][0] + b0, c[mf][nf][1] + b1);
                        *(float2*)&hb[(size_t)(m + 8) * HD] =
                            make_float2(c[mf][nf][2] + b0, c[mf][nf][3] + b1);
                    }
            }
#pragma unroll
            for (int mf = 0; mf < 2; ++mf)
#pragma unroll
                for (int nf = 0; nf < 4; ++nf)
#pragma unroll
                    for (int r2 = 0; r2 < 4; ++r2) c[mf][nf][r2] = 0.f;
        }

        if (it < 10)       cpwait1();
        else if (it == 10) cpwait0();
        __syncthreads();
    }
}

// ------------------------------------------------------------------
// Kernel 2: neighborhood attention (circular). R3/R4-proven hot loop:
// 16x16 tile, 256 thr, thread = 1 px, TWO passes of 16 channels with
// stride-20 v tile (41KB static smem; pass-2 global reload hits L1).
// Epilogue: bf16 hi/lo split, COALESCED stores in (b,h,p,d) layout.
// ------------------------------------------------------------------
__global__ __launch_bounds__(256) void attn_kernel(const float* __restrict__ rpb)
{
    __shared__ __align__(16) float ds[22 * 24];
    __shared__ __align__(16) float rs[KK2];
    __shared__ __align__(16) float vs[484 * 20];

    const int bh = blockIdx.z;        // b*4 + h
    const int h  = bh & 3;
    const int b  = bh >> 2;
    const int y0 = blockIdx.y * 16;
    const int x0 = blockIdx.x * 16;
    const int tid = threadIdx.x;

    for (int idx = tid; idx < 484; idx += 256) {
        int r  = idx / 22, cc = idx - r * 22;
        int gy = y0 + r;  if (gy >= HH) gy -= HH;
        int gx = x0 + cc; if (gx >= WW) gx -= WW;
        ds[r * 24 + cc] = g_dot[(size_t)bh * HWSZ + gy * WW + gx];
    }
    if (tid < KK2) rs[tid] = rpb[h * KK2 + tid];

    const float* vbase = g_v + (size_t)bh * (HWSZ * HD);

    // v channels 0..15
    for (int idx = tid; idx < 484 * 4; idx += 256) {
        int pix = idx >> 2, gg = idx & 3;
        int r  = pix / 22, cc = pix - r * 22;
        int gy = y0 + r;  if (gy >= HH) gy -= HH;
        int gx = x0 + cc; if (gx >= WW) gx -= WW;
        *(float4*)&vs[pix * 20 + gg * 4] =
            *(const float4*)&vbase[(size_t)(gy * WW + gx) * HD + gg * 4];
    }
    __syncthreads();

    const int ty = tid >> 4, tx = tid & 15;

    float wgt[KK2];
    float mx = -1e30f;
#pragma unroll
    for (int i = 0; i < 7; ++i)
#pragma unroll
        for (int j = 0; j < 7; ++j) {
            float val = ds[(ty + i) * 24 + tx + j] + rs[i * 7 + j];
            wgt[i * 7 + j] = val;
            mx = fmaxf(mx, val);
        }
    float sum = 0.f;
#pragma unroll
    for (int n = 0; n < KK2; ++n) { wgt[n] = __expf(wgt[n] - mx); sum += wgt[n]; }
    const float inv = 1.f / sum;

    const int p = (y0 + ty) * WW + (x0 + tx);
    // head-blocked output: (b,h,p,d)
    const size_t obase = ((size_t)(b * NH + h) * HWSZ + p) * HD;

#pragma unroll
    for (int half = 0; half < 2; ++half) {
        if (half == 1) {
            __syncthreads();
            for (int idx = tid; idx < 484 * 4; idx += 256) {
                int pix = idx >> 2, gg = idx & 3;
                int r  = pix / 22, cc = pix - r * 22;
                int gy = y0 + r;  if (gy >= HH) gy -= HH;
                int gx = x0 + cc; if (gx >= WW) gx -= WW;
                *(float4*)&vs[pix * 20 + gg * 4] =
                    *(const float4*)&vbase[(size_t)(gy * WW + gx) * HD + 16 + gg * 4];
            }
            __syncthreads();
        }

        float4 acc[4];
#pragma unroll
        for (int gg = 0; gg < 4; ++gg) acc[gg] = make_float4(0.f, 0.f, 0.f, 0.f);
#pragma unroll
        for (int i = 0; i < 7; ++i)
#pragma unroll
            for (int j = 0; j < 7; ++j) {
                float wt  = wgt[i * 7 + j];
                int   pix = (ty + i) * 22 + (tx + j);
#pragma unroll
                for (int gg = 0; gg < 4; ++gg) {
                    float4 vv = *(const float4*)&vs[pix * 20 + gg * 4];
                    acc[gg].x = fmaf(wt, vv.x, acc[gg].x);
                    acc[gg].y = fmaf(wt, vv.y, acc[gg].y);
                    acc[gg].z = fmaf(wt, vv.z, acc[gg].z);
                    acc[gg].w = fmaf(wt, vv.w, acc[gg].w);
                }
            }

        unsigned hi_u[8], lo_u[8];
#pragma unroll
        for (int gg = 0; gg < 4; ++gg) {
            float f[4] = { acc[gg].x * inv, acc[gg].y * inv,
                           acc[gg].z * inv, acc[gg].w * inv };
#pragma unroll
            for (int e = 0; e < 2; ++e) {
                float f0 = f[e * 2], f1 = f[e * 2 + 1];
                __nv_bfloat16 h0 = __float2bfloat16(f0);
                __nv_bfloat16 h1 = __float2bfloat16(f1);
                __nv_bfloat16 l0 = __float2bfloat16(f0 - __bfloat162float(h0));
                __nv_bfloat16 l1 = __float2bfloat16(f1 - __bfloat162float(h1));
                hi_u[gg * 2 + e] = bfpack(h0, h1);
                lo_u[gg * 2 + e] = bfpack(l0, l1);
            }
        }
        size_t ob = obase + half * 16;
        *(uint4*)&g_ath[ob]     = make_uint4(hi_u[0], hi_u[1], hi_u[2], hi_u[3]);
        *(uint4*)&g_ath[ob + 8] = make_uint4(hi_u[4], hi_u[5], hi_u[6], hi_u[7]);
        *(uint4*)&g_atl[ob]     = make_uint4(lo_u[0], lo_u[1], lo_u[2], lo_u[3]);
        *(uint4*)&g_atl[ob + 8] = make_uint4(lo_u[4], lo_u[5], lo_u[6], lo_u[7]);
    }
}

// ------------------------------------------------------------------
// Kernel 3: proj GEMM + transpose. R8 structure; issueA re-addressed
// for head-blocked att layout: k = kt*32 + c4*8 -> head kt, d = c4*8.
// ------------------------------------------------------------------
#define PB_H 0
#define PB_L 34816
#define PA0  69632
#define PBUF 20480
#define PSM  131072

__device__ __forceinline__ void proj_issueA(unsigned sb, int t, int bq, int hw0, int kt)
{
    const int buf = kt % 3;
    const int mrow = t >> 2, c4 = t & 3;
    unsigned ad = sb + PA0 + buf * PBUF + mrow * 80 + c4 * 16;
    size_t off = ((size_t)(bq * NH + kt) * HWSZ + hw0 + mrow) * HD + c4 * 8;
    cpa16(ad,         g_ath + off);
    cpa16(ad + 10240, g_atl + off);
}

__global__ __launch_bounds__(512) void proj_kernel(
    const float* __restrict__ pb, float* __restrict__ out)
{
    extern __shared__ __align__(16) char sm[];
    const unsigned sb = (unsigned)__cvta_generic_to_shared(sm);

    const int mtile = blockIdx.x;
    const int bq    = mtile / 98;
    const int hw0   = (mtile - bq * 98) * 128;
    const int t     = threadIdx.x;
    const int l     = t & 31, w = t >> 5;
    const int wm    = w >> 2, wn = w & 3;
    const int g     = l >> 3, i = l & 7;

    {
#pragma unroll
        for (int j = 0; j < 4; ++j) {
            int cid = t + j * 512;
            int row = cid >> 4, c16 = cid & 15;
            cpa16(sb + PB_H + row * 272 + c16 * 16, g_pwh + (size_t)row * CH + c16 * 8);
            cpa16(sb + PB_L + row * 272 + c16 * 16, g_pwl + (size_t)row * CH + c16 * 8);
        }
        proj_issueA(sb, t, bq, hw0, 0);
        cpcommit();
        proj_issueA(sb, t, bq, hw0, 1);
        cpcommit();
        cpwait1();
        __syncthreads();
    }

    float c[2][4][4];
#pragma unroll
    for (int mf = 0; mf < 2; ++mf)
#pragma unroll
        for (int nf = 0; nf < 4; ++nf)
#pragma unroll
            for (int r2 = 0; r2 < 4; ++r2) c[mf][nf][r2] = 0.f;

    for (int kt = 0; kt < 4; ++kt) {
        const int buf = kt % 3;
        if (kt < 2) { proj_issueA(sb, t, bq, hw0, kt + 2); cpcommit(); }

        const unsigned Ab = sb + PA0 + buf * PBUF;
#pragma unroll
        for (int kb = 0; kb < 32; kb += 16) {
            unsigned ah[2][4], al_[2][4], bh[4][2], bl[4][2];
#pragma unroll
            for (int mf = 0; mf < 2; ++mf) {
                int mrow = wm * 32 + mf * 16 + ((g & 1) << 3) + i;
                unsigned ad = Ab + mrow * 80 + kb * 2 + ((g >> 1) << 4);
                ldsm4(ah[mf], ad);
                ldsm4(al_[mf], ad + 10240);
            }
#pragma unroll
            for (int ng = 0; ng < 2; ++ng) {
                int nrow = wn * 32 + ng * 16 + ((g >> 1) << 3) + i;
                unsigned bd = sb + PB_H + nrow * 272 + (kt * 32 + kb) * 2 + ((g & 1) << 4);
                unsigned r[4];
                ldsm4(r, bd);
                bh[ng * 2][0] = r[0]; bh[ng * 2][1] = r[1];
                bh[ng * 2 + 1][0] = r[2]; bh[ng * 2 + 1][1] = r[3];
                ldsm4(r, bd + (PB_L - PB_H));
                bl[ng * 2][0] = r[0]; bl[ng * 2][1] = r[1];
                bl[ng * 2 + 1][0] = r[2]; bl[ng * 2 + 1][1] = r[3];
            }
#pragma unroll
            for (int mf = 0; mf < 2; ++mf)
#pragma unroll
                for (int nf = 0; nf < 4; ++nf) {
                    mma16816(c[mf][nf], ah[mf], bh[nf]);
                    mma16816(c[mf][nf], ah[mf], bl[nf]);
                    mma16816(c[mf][nf], al_[mf], bh[nf]);
                }
        }
        if (kt < 2)       cpwait1();
        else if (kt == 2) cpwait0();
        __syncthreads();
    }

    const int hw0e = hw0;
    float* eb = (float*)(sm + PA0);

    for (int nc = 0; nc < 4; ++nc) {
        if (wn == nc) {
#pragma unroll
            for (int mf = 0; mf < 2; ++mf)
#pragma unroll
                for (int nf = 0; nf < 4; ++nf) {
                    int nl = nf * 8 + (l & 3) * 2;
                    int m  = wm * 32 + mf * 16 + (l >> 2);
                    eb[nl * 132 + m]           = c[mf][nf][0];
                    eb[(nl + 1) * 132 + m]     = c[mf][nf][1];
                    eb[nl * 132 + m + 8]       = c[mf][nf][2];
                    eb[(nl + 1) * 132 + m + 8] = c[mf][nf][3];
                }
        }
        __syncthreads();
        {
            int nl = t >> 4;
            int mm = (t & 15) * 8;
            int ng2 = nc * 32 + nl;
            float bias = pb[ng2];
            float* orow = out + (size_t)(bq * CH + ng2) * HWSZ + hw0e;
#pragma unroll
            for (int j = 0; j < 2; ++j) {
                float4 v = *(float4*)&eb[nl * 132 + mm + j * 4];
                v.x += bias; v.y += bias; v.z += bias; v.w += bias;
                *(float4*)&orow[mm + j * 4] = v;
            }
        }
        __syncthreads();
    }
}

// ------------------------------------------------------------------
extern "C" void kernel_launch(void* const* d_in, const int* in_sizes, int n_in,
                              void* d_out, int out_size)
{
    const float* x      = (const float*)d_in[0];
    const float* qkv_w  = (const float*)d_in[1];
    const float* qkv_b  = (const float*)d_in[2];
    const float* rpb    = (const float*)d_in[3];
    const float* proj_w = (const float*)d_in[4];
    const float* proj_b = (const float*)d_in[5];
    float* out = (float*)d_out;

    cudaFuncSetAttribute(qkvdot_kernel,
                         cudaFuncAttributeMaxDynamicSharedMemorySize, QSM);
    cudaFuncSetAttribute(proj_kernel,
                         cudaFuncAttributeMaxDynamicSharedMemorySize, PSM);

    split_w_kernel<<<(3 * CH * CH + CH * CH) / 1024, 256>>>(qkv_w, proj_w);
    qkvdot_kernel<<<784, 512, QSM>>>(x, qkv_b);
    attn_kernel<<<dim3(7, 7, 32), 256>>>(rpb);
    proj_kernel<<<784, 512, PSM>>>(proj_b, out);
}

// round 11
// speedup vs baseline: 1.5987x; 1.0871x over previous
#include <cuda_runtime.h>
#include <cuda_bf16.h>

#define BATCH 8
#define CH    128
#define HH    112
#define WW    112
#define HWSZ  12544     // 112*112
#define NH    4
#define HD    32
#define KS    7
#define KK2   49
#define SCALE 0.17677669529663687f   // 32^-0.5

// Persistent scratch (static device allocations).
static __device__ __align__(16) __nv_bfloat16 g_wqh[3*CH*CH];        // qkv_w hi, [n][k]
static __device__ __align__(16) __nv_bfloat16 g_wql[3*CH*CH];
static __device__ __align__(16) __nv_bfloat16 g_pwh[CH*CH];          // proj_w hi
static __device__ __align__(16) __nv_bfloat16 g_pwl[CH*CH];
static __device__ __align__(16) float g_v  [BATCH*NH*HWSZ*HD];       // (b,h,p,d)
static __device__ __align__(16) float g_dot[BATCH*NH*HWSZ];          // (b,h,p)
// att hi/lo in HEAD-BLOCKED layout (b,h,p,d): attn stores coalesce.
static __device__ __align__(16) __nv_bfloat16 g_ath[BATCH*NH*HWSZ*HD];
static __device__ __align__(16) __nv_bfloat16 g_atl[BATCH*NH*HWSZ*HD];

// ---------------- helpers ----------------------------------------

__device__ __forceinline__ unsigned bfpack(__nv_bfloat16 a, __nv_bfloat16 b) {
    return (unsigned)__bfloat16_as_ushort(a) | ((unsigned)__bfloat16_as_ushort(b) << 16);
}

__device__ __forceinline__ void split4(float4 v, uint2& hi, uint2& lo) {
    __nv_bfloat16 hx = __float2bfloat16(v.x);
    __nv_bfloat16 hy = __float2bfloat16(v.y);
    __nv_bfloat16 hz = __float2bfloat16(v.z);
    __nv_bfloat16 hw = __float2bfloat16(v.w);
    __nv_bfloat16 lx = __float2bfloat16(v.x - __bfloat162float(hx));
    __nv_bfloat16 ly = __float2bfloat16(v.y - __bfloat162float(hy));
    __nv_bfloat16 lz = __float2bfloat16(v.z - __bfloat162float(hz));
    __nv_bfloat16 lw = __float2bfloat16(v.w - __bfloat162float(hw));
    hi.x = bfpack(hx, hy); hi.y = bfpack(hz, hw);
    lo.x = bfpack(lx, ly); lo.y = bfpack(lz, lw);
}

__device__ __forceinline__ void ldsm4(unsigned* r, unsigned addr) {
    asm volatile("ldmatrix.sync.aligned.m8n8.x4.shared.b16 {%0,%1,%2,%3}, [%4];"
                 : "=r"(r[0]), "=r"(r[1]), "=r"(r[2]), "=r"(r[3]) : "r"(addr));
}
__device__ __forceinline__ void ldsm4t(unsigned* r, unsigned addr) {
    asm volatile("ldmatrix.sync.aligned.m8n8.x4.trans.shared.b16 {%0,%1,%2,%3}, [%4];"
                 : "=r"(r[0]), "=r"(r[1]), "=r"(r[2]), "=r"(r[3]) : "r"(addr));
}
__device__ __forceinline__ void mma16816(float* c, const unsigned* a, const unsigned* b) {
    asm volatile(
        "mma.sync.aligned.m16n8k16.row.col.f32.bf16.bf16.f32 "
        "{%0,%1,%2,%3}, {%4,%5,%6,%7}, {%8,%9}, {%0,%1,%2,%3};"
        : "+f"(c[0]), "+f"(c[1]), "+f"(c[2]), "+f"(c[3])
        : "r"(a[0]), "r"(a[1]), "r"(a[2]), "r"(a[3]), "r"(b[0]), "r"(b[1]));
}

__device__ __forceinline__ void cpa16(unsigned dst, const void* src) {
    asm volatile("cp.async.cg.shared.global [%0], [%1], 16;" :: "r"(dst), "l"(src));
}
__device__ __forceinline__ void cpcommit() {
    asm volatile("cp.async.commit_group;");
}
__device__ __forceinline__ void cpwait1() {
    asm volatile("cp.async.wait_group 1;");
}
__device__ __forceinline__ void cpwait0() {
    asm volatile("cp.async.wait_group 0;");
}

// ------------------------------------------------------------------
// Pre-split kernel: weights fp32 -> bf16 hi/lo (tiny)
// ------------------------------------------------------------------
__global__ __launch_bounds__(256) void split_w_kernel(
    const float* __restrict__ qw, const float* __restrict__ pw)
{
    int i = (blockIdx.x * 256 + threadIdx.x) * 4;
    uint2 hi, lo;
    if (i < 3 * CH * CH) {
        float4 v = *(const float4*)&qw[i];
        split4(v, hi, lo);
        *(uint2*)&g_wqh[i] = hi;
        *(uint2*)&g_wql[i] = lo;
    } else {
        int j = i - 3 * CH * CH;
        float4 v = *(const float4*)&pw[j];
        split4(v, hi, lo);
        *(uint2*)&g_pwh[j] = hi;
        *(uint2*)&g_pwl[j] = lo;
    }
}

// ------------------------------------------------------------------
// Kernel 1: fused QKV GEMM + q.k dot. bf16 3-term split.
// M-tile 128, 512 thr, 4x4 warps of 32x32.  (byte-identical to R10)
// ------------------------------------------------------------------
#define QA_H 0
#define QA_L 34816
#define QB0  69632
#define QBUF 20480
#define QSM  131072

__device__ __forceinline__ void qkv_issueB(unsigned sb, int t, int it)
{
    const int nt = it >> 2, kt = it & 3, buf = it % 3;
    const int nrow = t >> 2, c4 = t & 3;
    unsigned bd = sb + QB0 + buf * QBUF + nrow * 80 + c4 * 16;
    size_t off = (size_t)(nt * 128 + nrow) * CH + kt * 32 + c4 * 8;
    cpa16(bd,         g_wqh + off);
    cpa16(bd + 10240, g_wql + off);
}

__global__ __launch_bounds__(512) void qkvdot_kernel(
    const float* __restrict__ x, const float* __restrict__ bias)
{
    extern __shared__ __align__(16) char sm[];
    const unsigned sb = (unsigned)__cvta_generic_to_shared(sm);

    const int mtile = blockIdx.x;            // 0..783
    const int b     = mtile / 98;
    const int hw0   = (mtile - b * 98) * 128;
    const int t     = threadIdx.x;
    const int l     = t & 31, w = t >> 5;
    const int wm    = w >> 2, wn = w & 3;
    const int g     = l >> 3, i = l & 7;

    // ---- prologue: B(0), B(1) via cp.async; A fp32 load + split ----
    {
        qkv_issueB(sb, t, 0);
        cpcommit();
        qkv_issueB(sb, t, 1);
        cpcommit();

        const float* xb = x + (size_t)b * (CH * HWSZ) + hw0;
        const int m4 = (t & 31) * 4;
        const int kr = t >> 5;               // 0..15
        float4 av[8];
#pragma unroll
        for (int j = 0; j < 8; ++j)
            av[j] = *(const float4*)(xb + (size_t)(kr + j * 16) * HWSZ + m4);
#pragma unroll
        for (int j = 0; j < 8; ++j) {
            uint2 hi, lo;
            split4(av[j], hi, lo);
            unsigned ad = sb + QA_H + (kr + j * 16) * 272 + m4 * 2;
            *(uint2*)__cvta_shared_to_generic(ad) = hi;
            *(uint2*)__cvta_shared_to_generic(ad + (QA_L - QA_H)) = lo;
        }
        cpwait1();
        __syncthreads();
    }

    float c[2][4][4];
    float qreg[2][4][4];
#pragma unroll
    for (int mf = 0; mf < 2; ++mf)
#pragma unroll
        for (int nf = 0; nf < 4; ++nf)
#pragma unroll
            for (int r2 = 0; r2 < 4; ++r2) c[mf][nf][r2] = 0.f;

    for (int it = 0; it < 12; ++it) {
        const int nt = it >> 2, kt = it & 3, buf = it % 3;

        if (it < 10) { qkv_issueB(sb, t, it + 2); cpcommit(); }

        const unsigned Bb = sb + QB0 + buf * QBUF;
#pragma unroll
        for (int kb = 0; kb < 32; kb += 16) {
            unsigned ah[2][4], al_[2][4], bh[4][2], bl[4][2];
#pragma unroll
            for (int mf = 0; mf < 2; ++mf) {
                int row  = kt * 32 + kb + i + ((g >> 1) << 3);
                int mcol = wm * 32 + mf * 16 + ((g & 1) << 3);
                unsigned ad = sb + QA_H + row * 272 + mcol * 2;
                ldsm4t(ah[mf], ad);
                ldsm4t(al_[mf], ad + (QA_L - QA_H));
            }
#pragma unroll
            for (int ng = 0; ng < 2; ++ng) {
                int nrow = wn * 32 + ng * 16 + ((g >> 1) << 3) + i;
                unsigned bd = Bb + nrow * 80 + kb * 2 + ((g & 1) << 4);
                unsigned r[4];
                ldsm4(r, bd);
                bh[ng * 2][0] = r[0]; bh[ng * 2][1] = r[1];
                bh[ng * 2 + 1][0] = r[2]; bh[ng * 2 + 1][1] = r[3];
                ldsm4(r, bd + 10240);
                bl[ng * 2][0] = r[0]; bl[ng * 2][1] = r[1];
                bl[ng * 2 + 1][0] = r[2]; bl[ng * 2 + 1][1] = r[3];
            }
#pragma unroll
            for (int mf = 0; mf < 2; ++mf)
#pragma unroll
                for (int nf = 0; nf < 4; ++nf) {
                    mma16816(c[mf][nf], ah[mf], bh[nf]);
                    mma16816(c[mf][nf], ah[mf], bl[nf]);
                    mma16816(c[mf][nf], al_[mf], bh[nf]);
                }
        }

        if (kt == 3) {
            if (nt == 0) {
#pragma unroll
                for (int mf = 0; mf < 2; ++mf)
#pragma unroll
                    for (int nf = 0; nf < 4; ++nf) {
                        int n = wn * 32 + nf * 8 + (l & 3) * 2;
                        float b0 = bias[n], b1 = bias[n + 1];
                        qreg[mf][nf][0] = c[mf][nf][0] + b0;
                        qreg[mf][nf][1] = c[mf][nf][1] + b1;
                        qreg[mf][nf][2] = c[mf][nf][2] + b0;
                        qreg[mf][nf][3] = c[mf][nf][3] + b1;
                    }
            } else if (nt == 1) {
#pragma unroll
                for (int mf = 0; mf < 2; ++mf) {
                    float s0 = 0.f, s1 = 0.f;
                    int m = wm * 32 + mf * 16 + (l >> 2);
#pragma unroll
                    for (int nf = 0; nf < 4; ++nf) {
                        int n = wn * 32 + nf * 8 + (l & 3) * 2;
                        float b0 = bias[128 + n], b1 = bias[128 + n + 1];
                        s0 += qreg[mf][nf][0] * (c[mf][nf][0] + b0)
                            + qreg[mf][nf][1] * (c[mf][nf][1] + b1);
                        s1 += qreg[mf][nf][2] * (c[mf][nf][2] + b0)
                            + qreg[mf][nf][3] * (c[mf][nf][3] + b1);
                    }
                    s0 += __shfl_xor_sync(0xffffffffu, s0, 1);
                    s0 += __shfl_xor_sync(0xffffffffu, s0, 2);
                    s1 += __shfl_xor_sync(0xffffffffu, s1, 1);
                    s1 += __shfl_xor_sync(0xffffffffu, s1, 2);
                    if ((l & 3) == 0) {
                        size_t base = (size_t)(b * NH + wn) * HWSZ + hw0;
                        g_dot[base + m]     = s0 * SCALE;
                        g_dot[base + m + 8] = s1 * SCALE;
                    }
                }
            } else {
#pragma unroll
                for (int mf = 0; mf < 2; ++mf)
#pragma unroll
                    for (int nf = 0; nf < 4; ++nf) {
                        int n = wn * 32 + nf * 8 + (l & 3) * 2;
                        int m = wm * 32 + mf * 16 + (l >> 2);
                        float b0 = bias[256 + n], b1 = bias[256 + n + 1];
                        int d = n & 31;
                        float* hb = g_v + ((size_t)(b * NH + wn) * HWSZ + hw0) * HD + d;
                        *(float2*)&hb[(size_t)m * HD] =
                            make_float2(c[mf][nf][0] + b0, c[mf][nf][1] + b1);
                        *(float2*)&hb[(size_t)(m + 8) * HD] =
                            make_float2(c[mf][nf][2] + b0, c[mf][nf][3] + b1);
                    }
            }
#pragma unroll
            for (int mf = 0; mf < 2; ++mf)
#pragma unroll
                for (int nf = 0; nf < 4; ++nf)
#pragma unroll
                    for (int r2 = 0; r2 < 4; ++r2) c[mf][nf][r2] = 0.f;
        }

        if (it < 10)       cpwait1();
        else if (it == 10) cpwait0();
        __syncthreads();
    }
}

// ------------------------------------------------------------------
// Kernel 2: neighborhood attention (circular), vertical 2-px strip.
// Block = 16x16 px, 128 threads; thread = (x, rows 2r,2r+1).
// The two stacked pixels share window columns: v reads drop from
// 49 -> 28 positions per output (1.75x less smem-port traffic).
// Lane->x mapping and stride-20 float4 v tile identical to R10
// (proven conflict-free). Two 16-ch passes. wgt[2][49] in regs
// (1/sum folded in). Coalesced bf16 hi/lo stores in (b,h,p,d).
// ------------------------------------------------------------------
__global__ __launch_bounds__(128) void attn_kernel(const float* __restrict__ rpb)
{
    __shared__ __align__(16) float ds[22 * 24];
    __shared__ __align__(16) float rs[KK2];
    __shared__ __align__(16) float vs[484 * 20];

    const int bh = blockIdx.z;        // b*4 + h
    const int h  = bh & 3;
    const int b  = bh >> 2;
    const int y0 = blockIdx.y * 16;
    const int x0 = blockIdx.x * 16;
    const int tid = threadIdx.x;

    for (int idx = tid; idx < 484; idx += 128) {
        int r  = idx / 22, cc = idx - r * 22;
        int gy = y0 + r;  if (gy >= HH) gy -= HH;
        int gx = x0 + cc; if (gx >= WW) gx -= WW;
        ds[r * 24 + cc] = g_dot[(size_t)bh * HWSZ + gy * WW + gx];
    }
    if (tid < KK2) rs[tid] = rpb[h * KK2 + tid];

    const float* vbase = g_v + (size_t)bh * (HWSZ * HD);

    // v channels 0..15
    for (int idx = tid; idx < 484 * 4; idx += 128) {
        int pix = idx >> 2, gg = idx & 3;
        int r  = pix / 22, cc = pix - r * 22;
        int gy = y0 + r;  if (gy >= HH) gy -= HH;
        int gx = x0 + cc; if (gx >= WW) gx -= WW;
        *(float4*)&vs[pix * 20 + gg * 4] =
            *(const float4*)&vbase[(size_t)(gy * WW + gx) * HD + gg * 4];
    }
    __syncthreads();

    const int ty2 = tid >> 4;          // 0..7 -> rows 2*ty2, 2*ty2+1
    const int tx  = tid & 15;

    // softmax for both pixels, 1/sum folded into weights
    float wgt[2][KK2];
#pragma unroll
    for (int px = 0; px < 2; ++px) {
        float mx = -1e30f;
#pragma unroll
        for (int i = 0; i < 7; ++i)
#pragma unroll
            for (int j = 0; j < 7; ++j) {
                float val = ds[(2 * ty2 + px + i) * 24 + tx + j] + rs[i * 7 + j];
                wgt[px][i * 7 + j] = val;
                mx = fmaxf(mx, val);
            }
        float sum = 0.f;
#pragma unroll
        for (int n = 0; n < KK2; ++n) { wgt[px][n] = __expf(wgt[px][n] - mx); sum += wgt[px][n]; }
        float inv = 1.f / sum;
#pragma unroll
        for (int n = 0; n < KK2; ++n) wgt[px][n] *= inv;
    }

    const int p0 = (y0 + 2 * ty2) * WW + (x0 + tx);
    const size_t ob0 = ((size_t)(b * NH + h) * HWSZ + p0) * HD;        // px0
    const size_t ob1 = ob0 + (size_t)WW * HD;                          // px1 (row+1)

#pragma unroll
    for (int half = 0; half < 2; ++half) {
        if (half == 1) {
            __syncthreads();
            for (int idx = tid; idx < 484 * 4; idx += 128) {
                int pix = idx >> 2, gg = idx & 3;
                int r  = pix / 22, cc = pix - r * 22;
                int gy = y0 + r;  if (gy >= HH) gy -= HH;
                int gx = x0 + cc; if (gx >= WW) gx -= WW;
                *(float4*)&vs[pix * 20 + gg * 4] =
                    *(const float4*)&vbase[(size_t)(gy * WW + gx) * HD + 16 + gg * 4];
            }
            __syncthreads();
        }

        float4 acc0[4], acc1[4];
#pragma unroll
        for (int gg = 0; gg < 4; ++gg) {
            acc0[gg] = make_float4(0.f, 0.f, 0.f, 0.f);
            acc1[gg] = make_float4(0.f, 0.f, 0.f, 0.f);
        }
        // 8 shared window rows; each loaded float4 feeds both pixels
#pragma unroll
        for (int i = 0; i < 8; ++i)
#pragma unroll
            for (int j = 0; j < 7; ++j) {
                int pix = (2 * ty2 + i) * 22 + (tx + j);
                float w0 = (i < 7) ? wgt[0][i * 7 + j] : 0.f;
                float w1 = (i >= 1) ? wgt[1][(i - 1) * 7 + j] : 0.f;
#pragma unroll
                for (int gg = 0; gg < 4; ++gg) {
                    float4 vv = *(const float4*)&vs[pix * 20 + gg * 4];
                    if (i < 7) {
                        acc0[gg].x = fmaf(w0, vv.x, acc0[gg].x);
                        acc0[gg].y = fmaf(w0, vv.y, acc0[gg].y);
                        acc0[gg].z = fmaf(w0, vv.z, acc0[gg].z);
                        acc0[gg].w = fmaf(w0, vv.w, acc0[gg].w);
                    }
                    if (i >= 1) {
                        acc1[gg].x = fmaf(w1, vv.x, acc1[gg].x);
                        acc1[gg].y = fmaf(w1, vv.y, acc1[gg].y);
                        acc1[gg].z = fmaf(w1, vv.z, acc1[gg].z);
                        acc1[gg].w = fmaf(w1, vv.w, acc1[gg].w);
                    }
                }
            }

        // store both pixels, this half (16 channels each)
#pragma unroll
        for (int px = 0; px < 2; ++px) {
            float4* acc = px ? acc1 : acc0;
            unsigned hi_u[8], lo_u[8];
#pragma unroll
            for (int gg = 0; gg < 4; ++gg) {
                float f[4] = { acc[gg].x, acc[gg].y, acc[gg].z, acc[gg].w };
#pragma unroll
                for (int e = 0; e < 2; ++e) {
                    float f0 = f[e * 2], f1 = f[e * 2 + 1];
                    __nv_bfloat16 h0 = __float2bfloat16(f0);
                    __nv_bfloat16 h1 = __float2bfloat16(f1);
                    __nv_bfloat16 l0 = __float2bfloat16(f0 - __bfloat162float(h0));
                    __nv_bfloat16 l1 = __float2bfloat16(f1 - __bfloat162float(h1));
                    hi_u[gg * 2 + e] = bfpack(h0, h1);
                    lo_u[gg * 2 + e] = bfpack(l0, l1);
                }
            }
            size_t ob = (px ? ob1 : ob0) + half * 16;
            *(uint4*)&g_ath[ob]     = make_uint4(hi_u[0], hi_u[1], hi_u[2], hi_u[3]);
            *(uint4*)&g_ath[ob + 8] = make_uint4(hi_u[4], hi_u[5], hi_u[6], hi_u[7]);
            *(uint4*)&g_atl[ob]     = make_uint4(lo_u[0], lo_u[1], lo_u[2], lo_u[3]);
            *(uint4*)&g_atl[ob + 8] = make_uint4(lo_u[4], lo_u[5], lo_u[6], lo_u[7]);
        }
    }
}

// ------------------------------------------------------------------
// Kernel 3: proj GEMM + transpose. (byte-identical to R10, 56us)
// ------------------------------------------------------------------
#define PB_H 0
#define PB_L 34816
#define PA0  69632
#define PBUF 20480
#define PSM  131072

__device__ __forceinline__ void proj_issueA(unsigned sb, int t, int bq, int hw0, int kt)
{
    const int buf = kt % 3;
    const int mrow = t >> 2, c4 = t & 3;
    unsigned ad = sb + PA0 + buf * PBUF + mrow * 80 + c4 * 16;
    size_t off = ((size_t)(bq * NH + kt) * HWSZ + hw0 + mrow) * HD + c4 * 8;
    cpa16(ad,         g_ath + off);
    cpa16(ad + 10240, g_atl + off);
}

__global__ __launch_bounds__(512) void proj_kernel(
    const float* __restrict__ pb, float* __restrict__ out)
{
    extern __shared__ __align__(16) char sm[];
    const unsigned sb = (unsigned)__cvta_generic_to_shared(sm);

    const int mtile = blockIdx.x;
    const int bq    = mtile / 98;
    const int hw0   = (mtile - bq * 98) * 128;
    const int t     = threadIdx.x;
    const int l     = t & 31, w = t >> 5;
    const int wm    = w >> 2, wn = w & 3;
    const int g     = l >> 3, i = l & 7;

    {
#pragma unroll
        for (int j = 0; j < 4; ++j) {
            int cid = t + j * 512;
            int row = cid >> 4, c16 = cid & 15;
            cpa16(sb + PB_H + row * 272 + c16 * 16, g_pwh + (size_t)row * CH + c16 * 8);
            cpa16(sb + PB_L + row * 272 + c16 * 16, g_pwl + (size_t)row * CH + c16 * 8);
        }
        proj_issueA(sb, t, bq, hw0, 0);
        cpcommit();
        proj_issueA(sb, t, bq, hw0, 1);
        cpcommit();
        cpwait1();
        __syncthreads();
    }

    float c[2][4][4];
#pragma unroll
    for (int mf = 0; mf < 2; ++mf)
#pragma unroll
        for (int nf = 0; nf < 4; ++nf)
#pragma unroll
            for (int r2 = 0; r2 < 4; ++r2) c[mf][nf][r2] = 0.f;

    for (int kt = 0; kt < 4; ++kt) {
        const int buf = kt % 3;
        if (kt < 2) { proj_issueA(sb, t, bq, hw0, kt + 2); cpcommit(); }

        const unsigned Ab = sb + PA0 + buf * PBUF;
#pragma unroll
        for (int kb = 0; kb < 32; kb += 16) {
            unsigned ah[2][4], al_[2][4], bh[4][2], bl[4][2];
#pragma unroll
            for (int mf = 0; mf < 2; ++mf) {
                int mrow = wm * 32 + mf * 16 + ((g & 1) << 3) + i;
                unsigned ad = Ab + mrow * 80 + kb * 2 + ((g >> 1) << 4);
                ldsm4(ah[mf], ad);
                ldsm4(al_[mf], ad + 10240);
            }
#pragma unroll
            for (int ng = 0; ng < 2; ++ng) {
                int nrow = wn * 32 + ng * 16 + ((g >> 1) << 3) + i;
                unsigned bd = sb + PB_H + nrow * 272 + (kt * 32 + kb) * 2 + ((g & 1) << 4);
                unsigned r[4];
                ldsm4(r, bd);
                bh[ng * 2][0] = r[0]; bh[ng * 2][1] = r[1];
                bh[ng * 2 + 1][0] = r[2]; bh[ng * 2 + 1][1] = r[3];
                ldsm4(r, bd + (PB_L - PB_H));
                bl[ng * 2][0] = r[0]; bl[ng * 2][1] = r[1];
                bl[ng * 2 + 1][0] = r[2]; bl[ng * 2 + 1][1] = r[3];
            }
#pragma unroll
            for (int mf = 0; mf < 2; ++mf)
#pragma unroll
                for (int nf = 0; nf < 4; ++nf) {
                    mma16816(c[mf][nf], ah[mf], bh[nf]);
                    mma16816(c[mf][nf], ah[mf], bl[nf]);
                    mma16816(c[mf][nf], al_[mf], bh[nf]);
                }
        }
        if (kt < 2)       cpwait1();
        else if (kt == 2) cpwait0();
        __syncthreads();
    }

    float* eb = (float*)(sm + PA0);

    for (int nc = 0; nc < 4; ++nc) {
        if (wn == nc) {
#pragma unroll
            for (int mf = 0; mf < 2; ++mf)
#pragma unroll
                for (int nf = 0; nf < 4; ++nf) {
                    int nl = nf * 8 + (l & 3) * 2;
                    int m  = wm * 32 + mf * 16 + (l >> 2);
                    eb[nl * 132 + m]           = c[mf][nf][0];
                    eb[(nl + 1) * 132 + m]     = c[mf][nf][1];
                    eb[nl * 132 + m + 8]       = c[mf][nf][2];
                    eb[(nl + 1) * 132 + m + 8] = c[mf][nf][3];
                }
        }
        __syncthreads();
        {
            int nl = t >> 4;
            int mm = (t & 15) * 8;
            int ng2 = nc * 32 + nl;
            float bias = pb[ng2];
            float* orow = out + (size_t)(bq * CH + ng2) * HWSZ + hw0;
#pragma unroll
            for (int j = 0; j < 2; ++j) {
                float4 v = *(float4*)&eb[nl * 132 + mm + j * 4];
                v.x += bias; v.y += bias; v.z += bias; v.w += bias;
                *(float4*)&orow[mm + j * 4] = v;
            }
        }
        __syncthreads();
    }
}

// ------------------------------------------------------------------
extern "C" void kernel_launch(void* const* d_in, const int* in_sizes, int n_in,
                              void* d_out, int out_size)
{
    const float* x      = (const float*)d_in[0];
    const float* qkv_w  = (const float*)d_in[1];
    const float* qkv_b  = (const float*)d_in[2];
    const float* rpb    = (const float*)d_in[3];
    const float* proj_w = (const float*)d_in[4];
    const float* proj_b = (const float*)d_in[5];
    float* out = (float*)d_out;

    cudaFuncSetAttribute(qkvdot_kernel,
                         cudaFuncAttributeMaxDynamicSharedMemorySize, QSM);
    cudaFuncSetAttribute(proj_kernel,
                         cudaFuncAttributeMaxDynamicSharedMemorySize, PSM);

    split_w_kernel<<<(3 * CH * CH + CH * CH) / 1024, 256>>>(qkv_w, proj_w);
    qkvdot_kernel<<<784, 512, QSM>>>(x, qkv_b);
    attn_kernel<<<dim3(7, 7, 32), 128>>>(rpb);
    proj_kernel<<<784, 512, PSM>>>(proj_b, out);
}

// round 12
// speedup vs baseline: 1.6452x; 1.0291x over previous
#include <cuda_runtime.h>
#include <cuda_bf16.h>

#define BATCH 8
#define CH    128
#define HH    112
#define WW    112
#define HWSZ  12544     // 112*112
#define NH    4
#define HD    32
#define KS    7
#define KK2   49
#define SCALE 0.17677669529663687f   // 32^-0.5

// Persistent scratch (static device allocations).
static __device__ __align__(16) __nv_bfloat16 g_wqh[3*CH*CH];        // qkv_w hi, [n][k]
static __device__ __align__(16) __nv_bfloat16 g_wql[3*CH*CH];
static __device__ __align__(16) __nv_bfloat16 g_pwh[CH*CH];          // proj_w hi
static __device__ __align__(16) __nv_bfloat16 g_pwl[CH*CH];
static __device__ __align__(16) float g_v  [BATCH*NH*HWSZ*HD];       // (b,h,p,d)
static __device__ __align__(16) float g_dot[BATCH*NH*HWSZ];          // (b,h,p)
// att hi/lo in HEAD-BLOCKED layout (b,h,p,d): attn stores coalesce.
static __device__ __align__(16) __nv_bfloat16 g_ath[BATCH*NH*HWSZ*HD];
static __device__ __align__(16) __nv_bfloat16 g_atl[BATCH*NH*HWSZ*HD];

// ---------------- helpers ----------------------------------------

__device__ __forceinline__ unsigned bfpack(__nv_bfloat16 a, __nv_bfloat16 b) {
    return (unsigned)__bfloat16_as_ushort(a) | ((unsigned)__bfloat16_as_ushort(b) << 16);
}

__device__ __forceinline__ void split4(float4 v, uint2& hi, uint2& lo) {
    __nv_bfloat16 hx = __float2bfloat16(v.x);
    __nv_bfloat16 hy = __float2bfloat16(v.y);
    __nv_bfloat16 hz = __float2bfloat16(v.z);
    __nv_bfloat16 hw = __float2bfloat16(v.w);
    __nv_bfloat16 lx = __float2bfloat16(v.x - __bfloat162float(hx));
    __nv_bfloat16 ly = __float2bfloat16(v.y - __bfloat162float(hy));
    __nv_bfloat16 lz = __float2bfloat16(v.z - __bfloat162float(hz));
    __nv_bfloat16 lw = __float2bfloat16(v.w - __bfloat162float(hw));
    hi.x = bfpack(hx, hy); hi.y = bfpack(hz, hw);
    lo.x = bfpack(lx, ly); lo.y = bfpack(lz, lw);
}

__device__ __forceinline__ void ldsm4(unsigned* r, unsigned addr) {
    asm volatile("ldmatrix.sync.aligned.m8n8.x4.shared.b16 {%0,%1,%2,%3}, [%4];"
                 : "=r"(r[0]), "=r"(r[1]), "=r"(r[2]), "=r"(r[3]) : "r"(addr));
}
__device__ __forceinline__ void ldsm4t(unsigned* r, unsigned addr) {
    asm volatile("ldmatrix.sync.aligned.m8n8.x4.trans.shared.b16 {%0,%1,%2,%3}, [%4];"
                 : "=r"(r[0]), "=r"(r[1]), "=r"(r[2]), "=r"(r[3]) : "r"(addr));
}
__device__ __forceinline__ void mma16816(float* c, const unsigned* a, const unsigned* b) {
    asm volatile(
        "mma.sync.aligned.m16n8k16.row.col.f32.bf16.bf16.f32 "
        "{%0,%1,%2,%3}, {%4,%5,%6,%7}, {%8,%9}, {%0,%1,%2,%3};"
        : "+f"(c[0]), "+f"(c[1]), "+f"(c[2]), "+f"(c[3])
        : "r"(a[0]), "r"(a[1]), "r"(a[2]), "r"(a[3]), "r"(b[0]), "r"(b[1]));
}

__device__ __forceinline__ void cpa16(unsigned dst, const void* src) {
    asm volatile("cp.async.cg.shared.global [%0], [%1], 16;" :: "r"(dst), "l"(src));
}
__device__ __forceinline__ void cpcommit() {
    asm volatile("cp.async.commit_group;");
}
__device__ __forceinline__ void cpwait1() {
    asm volatile("cp.async.wait_group 1;");
}
__device__ __forceinline__ void cpwait0() {
    asm volatile("cp.async.wait_group 0;");
}

// ------------------------------------------------------------------
// Pre-split kernel: weights fp32 -> bf16 hi/lo (tiny)
// ------------------------------------------------------------------
__global__ __launch_bounds__(256) void split_w_kernel(
    const float* __restrict__ qw, const float* __restrict__ pw)
{
    int i = (blockIdx.x * 256 + threadIdx.x) * 4;
    uint2 hi, lo;
    if (i < 3 * CH * CH) {
        float4 v = *(const float4*)&qw[i];
        split4(v, hi, lo);
        *(uint2*)&g_wqh[i] = hi;
        *(uint2*)&g_wql[i] = lo;
    } else {
        int j = i - 3 * CH * CH;
        float4 v = *(const float4*)&pw[j];
        split4(v, hi, lo);
        *(uint2*)&g_pwh[j] = hi;
        *(uint2*)&g_pwl[j] = lo;
    }
}

// ------------------------------------------------------------------
// Kernel 1: fused QKV GEMM + q.k dot. bf16 3-term split.
// BK=64: 6 phases (nt 0..2 x ktH 0..1), barriers halved vs BK=32.
// B chunks [128n][64k], 144B rows (144k mod 128 covers all eight
// 16B banksets -> ldsm conflict-free), 3-buffer ring via cp.async.
// A (x tile) resident, split in prologue. 512 thr, 4x4 warps, 32x32.
// ------------------------------------------------------------------
#define QA_H 0
#define QA_L 34816
#define QB0  69632
#define QBUF 36864
#define QSM  180224    // 69632 + 3*36864

__device__ __forceinline__ void qkv_issueB(unsigned sb, int t, int p)
{
    const int nt = p >> 1, ktH = p & 1, buf = p % 3;
    const int nrow = t >> 2, c4 = t & 3;
    unsigned bd = sb + QB0 + buf * QBUF + nrow * 144 + c4 * 32;
    size_t off = (size_t)(nt * 128 + nrow) * CH + ktH * 64 + c4 * 16;
    cpa16(bd,              g_wqh + off);
    cpa16(bd + 16,         g_wqh + off + 8);
    cpa16(bd + 18432,      g_wql + off);
    cpa16(bd + 18432 + 16, g_wql + off + 8);
}

__global__ __launch_bounds__(512) void qkvdot_kernel(
    const float* __restrict__ x, const float* __restrict__ bias)
{
    extern __shared__ __align__(16) char sm[];
    const unsigned sb = (unsigned)__cvta_generic_to_shared(sm);

    const int mtile = blockIdx.x;            // 0..783
    const int b     = mtile / 98;
    const int hw0   = (mtile - b * 98) * 128;
    const int t     = threadIdx.x;
    const int l     = t & 31, w = t >> 5;
    const int wm    = w >> 2, wn = w & 3;
    const int g     = l >> 3, i = l & 7;

    // ---- prologue: B(0), B(1) via cp.async; A fp32 load + split ----
    {
        qkv_issueB(sb, t, 0);
        cpcommit();
        qkv_issueB(sb, t, 1);
        cpcommit();

        const float* xb = x + (size_t)b * (CH * HWSZ) + hw0;
        const int m4 = (t & 31) * 4;
        const int kr = t >> 5;               // 0..15
        float4 av[8];
#pragma unroll
        for (int j = 0; j < 8; ++j)
            av[j] = *(const float4*)(xb + (size_t)(kr + j * 16) * HWSZ + m4);
#pragma unroll
        for (int j = 0; j < 8; ++j) {
            uint2 hi, lo;
            split4(av[j], hi, lo);
            unsigned ad = sb + QA_H + (kr + j * 16) * 272 + m4 * 2;
            *(uint2*)__cvta_shared_to_generic(ad) = hi;
            *(uint2*)__cvta_shared_to_generic(ad + (QA_L - QA_H)) = lo;
        }
        cpwait1();
        __syncthreads();
    }

    float c[2][4][4];
    float qreg[2][4][4];
#pragma unroll
    for (int mf = 0; mf < 2; ++mf)
#pragma unroll
        for (int nf = 0; nf < 4; ++nf)
#pragma unroll
            for (int r2 = 0; r2 < 4; ++r2) c[mf][nf][r2] = 0.f;

    for (int p = 0; p < 6; ++p) {
        const int nt = p >> 1, ktH = p & 1, buf = p % 3;

        if (p < 4) { qkv_issueB(sb, t, p + 2); cpcommit(); }

        const unsigned Bb = sb + QB0 + buf * QBUF;
#pragma unroll
        for (int kb = 0; kb < 64; kb += 16) {
            unsigned ah[2][4], al_[2][4], bh[4][2], bl[4][2];
#pragma unroll
            for (int mf = 0; mf < 2; ++mf) {
                int row  = ktH * 64 + kb + i + ((g >> 1) << 3);
                int mcol = wm * 32 + mf * 16 + ((g & 1) << 3);
                unsigned ad = sb + QA_H + row * 272 + mcol * 2;
                ldsm4t(ah[mf], ad);
                ldsm4t(al_[mf], ad + (QA_L - QA_H));
            }
#pragma unroll
            for (int ng = 0; ng < 2; ++ng) {
                int nrow = wn * 32 + ng * 16 + ((g >> 1) << 3) + i;
                unsigned bd = Bb + nrow * 144 + kb * 2 + ((g & 1) << 4);
                unsigned r[4];
                ldsm4(r, bd);
                bh[ng * 2][0] = r[0]; bh[ng * 2][1] = r[1];
                bh[ng * 2 + 1][0] = r[2]; bh[ng * 2 + 1][1] = r[3];
                ldsm4(r, bd + 18432);
                bl[ng * 2][0] = r[0]; bl[ng * 2][1] = r[1];
                bl[ng * 2 + 1][0] = r[2]; bl[ng * 2 + 1][1] = r[3];
            }
#pragma unroll
            for (int mf = 0; mf < 2; ++mf)
#pragma unroll
                for (int nf = 0; nf < 4; ++nf) {
                    mma16816(c[mf][nf], ah[mf], bh[nf]);
                    mma16816(c[mf][nf], ah[mf], bl[nf]);
                    mma16816(c[mf][nf], al_[mf], bh[nf]);
                }
        }

        if (ktH == 1) {
            if (nt == 0) {
#pragma unroll
                for (int mf = 0; mf < 2; ++mf)
#pragma unroll
                    for (int nf = 0; nf < 4; ++nf) {
                        int n = wn * 32 + nf * 8 + (l & 3) * 2;
                        float b0 = bias[n], b1 = bias[n + 1];
                        qreg[mf][nf][0] = c[mf][nf][0] + b0;
                        qreg[mf][nf][1] = c[mf][nf][1] + b1;
                        qreg[mf][nf][2] = c[mf][nf][2] + b0;
                        qreg[mf][nf][3] = c[mf][nf][3] + b1;
                    }
            } else if (nt == 1) {
#pragma unroll
                for (int mf = 0; mf < 2; ++mf) {
                    float s0 = 0.f, s1 = 0.f;
                    int m = wm * 32 + mf * 16 + (l >> 2);
#pragma unroll
                    for (int nf = 0; nf < 4; ++nf) {
                        int n = wn * 32 + nf * 8 + (l & 3) * 2;
                        float b0 = bias[128 + n], b1 = bias[128 + n + 1];
                        s0 += qreg[mf][nf][0] * (c[mf][nf][0] + b0)
                            + qreg[mf][nf][1] * (c[mf][nf][1] + b1);
                        s1 += qreg[mf][nf][2] * (c[mf][nf][2] + b0)
                            + qreg[mf][nf][3] * (c[mf][nf][3] + b1);
                    }
                    s0 += __shfl_xor_sync(0xffffffffu, s0, 1);
                    s0 += __shfl_xor_sync(0xffffffffu, s0, 2);
                    s1 += __shfl_xor_sync(0xffffffffu, s1, 1);
                    s1 += __shfl_xor_sync(0xffffffffu, s1, 2);
                    if ((l & 3) == 0) {
                        size_t base = (size_t)(b * NH + wn) * HWSZ + hw0;
                        g_dot[base + m]     = s0 * SCALE;
                        g_dot[base + m + 8] = s1 * SCALE;
                    }
                }
            } else {
#pragma unroll
                for (int mf = 0; mf < 2; ++mf)
#pragma unroll
                    for (int nf = 0; nf < 4; ++nf) {
                        int n = wn * 32 + nf * 8 + (l & 3) * 2;
                        int m = wm * 32 + mf * 16 + (l >> 2);
                        float b0 = bias[256 + n], b1 = bias[256 + n + 1];
                        int d = n & 31;
                        float* hb = g_v + ((size_t)(b * NH + wn) * HWSZ + hw0) * HD + d;
                        *(float2*)&hb[(size_t)m * HD] =
                            make_float2(c[mf][nf][0] + b0, c[mf][nf][1] + b1);
                        *(float2*)&hb[(size_t)(m + 8) * HD] =
                            make_float2(c[mf][nf][2] + b0, c[mf][nf][3] + b1);
                    }
            }
#pragma unroll
            for (int mf = 0; mf < 2; ++mf)
#pragma unroll
                for (int nf = 0; nf < 4; ++nf)
#pragma unroll
                    for (int r2 = 0; r2 < 4; ++r2) c[mf][nf][r2] = 0.f;
        }

        if (p < 4)       cpwait1();
        else if (p == 4) cpwait0();
        __syncthreads();
    }
}

// ------------------------------------------------------------------
// Kernel 2: neighborhood attention (circular), vertical 2-px strip.
// (byte-identical to R11 — frozen at its win)
// ------------------------------------------------------------------
__global__ __launch_bounds__(128) void attn_kernel(const float* __restrict__ rpb)
{
    __shared__ __align__(16) float ds[22 * 24];
    __shared__ __align__(16) float rs[KK2];
    __shared__ __align__(16) float vs[484 * 20];

    const int bh = blockIdx.z;        // b*4 + h
    const int h  = bh & 3;
    const int b  = bh >> 2;
    const int y0 = blockIdx.y * 16;
    const int x0 = blockIdx.x * 16;
    const int tid = threadIdx.x;

    for (int idx = tid; idx < 484; idx += 128) {
        int r  = idx / 22, cc = idx - r * 22;
        int gy = y0 + r;  if (gy >= HH) gy -= HH;
        int gx = x0 + cc; if (gx >= WW) gx -= WW;
        ds[r * 24 + cc] = g_dot[(size_t)bh * HWSZ + gy * WW + gx];
    }
    if (tid < KK2) rs[tid] = rpb[h * KK2 + tid];

    const float* vbase = g_v + (size_t)bh * (HWSZ * HD);

    for (int idx = tid; idx < 484 * 4; idx += 128) {
        int pix = idx >> 2, gg = idx & 3;
        int r  = pix / 22, cc = pix - r * 22;
        int gy = y0 + r;  if (gy >= HH) gy -= HH;
        int gx = x0 + cc; if (gx >= WW) gx -= WW;
        *(float4*)&vs[pix * 20 + gg * 4] =
            *(const float4*)&vbase[(size_t)(gy * WW + gx) * HD + gg * 4];
    }
    __syncthreads();

    const int ty2 = tid >> 4;          // 0..7 -> rows 2*ty2, 2*ty2+1
    const int tx  = tid & 15;

    float wgt[2][KK2];
#pragma unroll
    for (int px = 0; px < 2; ++px) {
        float mx = -1e30f;
#pragma unroll
        for (int i = 0; i < 7; ++i)
#pragma unroll
            for (int j = 0; j < 7; ++j) {
                float val = ds[(2 * ty2 + px + i) * 24 + tx + j] + rs[i * 7 + j];
                wgt[px][i * 7 + j] = val;
                mx = fmaxf(mx, val);
            }
        float sum = 0.f;
#pragma unroll
        for (int n = 0; n < KK2; ++n) { wgt[px][n] = __expf(wgt[px][n] - mx); sum += wgt[px][n]; }
        float inv = 1.f / sum;
#pragma unroll
        for (int n = 0; n < KK2; ++n) wgt[px][n] *= inv;
    }

    const int p0 = (y0 + 2 * ty2) * WW + (x0 + tx);
    const size_t ob0 = ((size_t)(b * NH + h) * HWSZ + p0) * HD;
    const size_t ob1 = ob0 + (size_t)WW * HD;

#pragma unroll
    for (int half = 0; half < 2; ++half) {
        if (half == 1) {
            __syncthreads();
            for (int idx = tid; idx < 484 * 4; idx += 128) {
                int pix = idx >> 2, gg = idx & 3;
                int r  = pix / 22, cc = pix - r * 22;
                int gy = y0 + r;  if (gy >= HH) gy -= HH;
                int gx = x0 + cc; if (gx >= WW) gx -= WW;
                *(float4*)&vs[pix * 20 + gg * 4] =
                    *(const float4*)&vbase[(size_t)(gy * WW + gx) * HD + 16 + gg * 4];
            }
            __syncthreads();
        }

        float4 acc0[4], acc1[4];
#pragma unroll
        for (int gg = 0; gg < 4; ++gg) {
            acc0[gg] = make_float4(0.f, 0.f, 0.f, 0.f);
            acc1[gg] = make_float4(0.f, 0.f, 0.f, 0.f);
        }
#pragma unroll
        for (int i = 0; i < 8; ++i)
#pragma unroll
            for (int j = 0; j < 7; ++j) {
                int pix = (2 * ty2 + i) * 22 + (tx + j);
                float w0 = (i < 7) ? wgt[0][i * 7 + j] : 0.f;
                float w1 = (i >= 1) ? wgt[1][(i - 1) * 7 + j] : 0.f;
#pragma unroll
                for (int gg = 0; gg < 4; ++gg) {
                    float4 vv = *(const float4*)&vs[pix * 20 + gg * 4];
                    if (i < 7) {
                        acc0[gg].x = fmaf(w0, vv.x, acc0[gg].x);
                        acc0[gg].y = fmaf(w0, vv.y, acc0[gg].y);
                        acc0[gg].z = fmaf(w0, vv.z, acc0[gg].z);
                        acc0[gg].w = fmaf(w0, vv.w, acc0[gg].w);
                    }
                    if (i >= 1) {
                        acc1[gg].x = fmaf(w1, vv.x, acc1[gg].x);
                        acc1[gg].y = fmaf(w1, vv.y, acc1[gg].y);
                        acc1[gg].z = fmaf(w1, vv.z, acc1[gg].z);
                        acc1[gg].w = fmaf(w1, vv.w, acc1[gg].w);
                    }
                }
            }

#pragma unroll
        for (int px = 0; px < 2; ++px) {
            float4* acc = px ? acc1 : acc0;
            unsigned hi_u[8], lo_u[8];
#pragma unroll
            for (int gg = 0; gg < 4; ++gg) {
                float f[4] = { acc[gg].x, acc[gg].y, acc[gg].z, acc[gg].w };
#pragma unroll
                for (int e = 0; e < 2; ++e) {
                    float f0 = f[e * 2], f1 = f[e * 2 + 1];
                    __nv_bfloat16 h0 = __float2bfloat16(f0);
                    __nv_bfloat16 h1 = __float2bfloat16(f1);
                    __nv_bfloat16 l0 = __float2bfloat16(f0 - __bfloat162float(h0));
                    __nv_bfloat16 l1 = __float2bfloat16(f1 - __bfloat162float(h1));
                    hi_u[gg * 2 + e] = bfpack(h0, h1);
                    lo_u[gg * 2 + e] = bfpack(l0, l1);
                }
            }
            size_t ob = (px ? ob1 : ob0) + half * 16;
            *(uint4*)&g_ath[ob]     = make_uint4(hi_u[0], hi_u[1], hi_u[2], hi_u[3]);
            *(uint4*)&g_ath[ob + 8] = make_uint4(hi_u[4], hi_u[5], hi_u[6], hi_u[7]);
            *(uint4*)&g_atl[ob]     = make_uint4(lo_u[0], lo_u[1], lo_u[2], lo_u[3]);
            *(uint4*)&g_atl[ob + 8] = make_uint4(lo_u[4], lo_u[5], lo_u[6], lo_u[7]);
        }
    }
}

// ------------------------------------------------------------------
// Kernel 3: proj GEMM + transpose. A AND B streamed per kt in one
// 40KB chunk (ring-3): prologue waits only chunk0 (~40KB) instead
// of full 136KB resident-B load. Chunk: Ah 0 / Al 10240 /
// Bh 20480 / Bl 30720, all 80B rows.
// ------------------------------------------------------------------
#define PBUF 40960
#define PSM  122880    // 3*40960

__device__ __forceinline__ void proj_issue(unsigned sb, int t, int bq, int hw0, int kt)
{
    const unsigned base = sb + (kt % 3) * PBUF;
    const int mrow = t >> 2, c4 = t & 3;
    unsigned ad = base + mrow * 80 + c4 * 16;
    size_t aoff = ((size_t)(bq * NH + kt) * HWSZ + hw0 + mrow) * HD + c4 * 8;
    cpa16(ad,         g_ath + aoff);
    cpa16(ad + 10240, g_atl + aoff);
    unsigned bd = base + 20480 + mrow * 80 + c4 * 16;
    size_t boff = (size_t)mrow * CH + kt * 32 + c4 * 8;
    cpa16(bd,         g_pwh + boff);
    cpa16(bd + 10240, g_pwl + boff);
}

__global__ __launch_bounds__(512) void proj_kernel(
    const float* __restrict__ pb, float* __restrict__ out)
{
    extern __shared__ __align__(16) char sm[];
    const unsigned sb = (unsigned)__cvta_generic_to_shared(sm);

    const int mtile = blockIdx.x;
    const int bq    = mtile / 98;
    const int hw0   = (mtile - bq * 98) * 128;
    const int t     = threadIdx.x;
    const int l     = t & 31, w = t >> 5;
    const int wm    = w >> 2, wn = w & 3;
    const int g     = l >> 3, i = l & 7;

    {
        proj_issue(sb, t, bq, hw0, 0);
        cpcommit();
        proj_issue(sb, t, bq, hw0, 1);
        cpcommit();
        cpwait1();
        __syncthreads();
    }

    float c[2][4][4];
#pragma unroll
    for (int mf = 0; mf < 2; ++mf)
#pragma unroll
        for (int nf = 0; nf < 4; ++nf)
#pragma unroll
            for (int r2 = 0; r2 < 4; ++r2) c[mf][nf][r2] = 0.f;

    for (int kt = 0; kt < 4; ++kt) {
        const unsigned Cb = sb + (kt % 3) * PBUF;
        if (kt < 2) { proj_issue(sb, t, bq, hw0, kt + 2); cpcommit(); }

#pragma unroll
        for (int kb = 0; kb < 32; kb += 16) {
            unsigned ah[2][4], al_[2][4], bh[4][2], bl[4][2];
#pragma unroll
            for (int mf = 0; mf < 2; ++mf) {
                int mrow = wm * 32 + mf * 16 + ((g & 1) << 3) + i;
                unsigned ad = Cb + mrow * 80 + kb * 2 + ((g >> 1) << 4);
                ldsm4(ah[mf], ad);
                ldsm4(al_[mf], ad + 10240);
            }
#pragma unroll
            for (int ng = 0; ng < 2; ++ng) {
                int nrow = wn * 32 + ng * 16 + ((g >> 1) << 3) + i;
                unsigned bd = Cb + 20480 + nrow * 80 + kb * 2 + ((g & 1) << 4);
                unsigned r[4];
                ldsm4(r, bd);
                bh[ng * 2][0] = r[0]; bh[ng * 2][1] = r[1];
                bh[ng * 2 + 1][0] = r[2]; bh[ng * 2 + 1][1] = r[3];
                ldsm4(r, bd + 10240);
                bl[ng * 2][0] = r[0]; bl[ng * 2][1] = r[1];
                bl[ng * 2 + 1][0] = r[2]; bl[ng * 2 + 1][1] = r[3];
            }
#pragma unroll
            for (int mf = 0; mf < 2; ++mf)
#pragma unroll
                for (int nf = 0; nf < 4; ++nf) {
                    mma16816(c[mf][nf], ah[mf], bh[nf]);
                    mma16816(c[mf][nf], ah[mf], bl[nf]);
                    mma16816(c[mf][nf], al_[mf], bh[nf]);
                }
        }
        if (kt < 2)       cpwait1();
        else if (kt == 2) cpwait0();
        __syncthreads();
    }

    // ---- epilogue: smem transpose (reuses ring area; post-sync) ----
    float* eb = (float*)sm;   // [32][132]

    for (int nc = 0; nc < 4; ++nc) {
        if (wn == nc) {
#pragma unroll
            for (int mf = 0; mf < 2; ++mf)
#pragma unroll
                for (int nf = 0; nf < 4; ++nf) {
                    int nl = nf * 8 + (l & 3) * 2;
                    int m  = wm * 32 + mf * 16 + (l >> 2);
                    eb[nl * 132 + m]           = c[mf][nf][0];
                    eb[(nl + 1) * 132 + m]     = c[mf][nf][1];
                    eb[nl * 132 + m + 8]       = c[mf][nf][2];
                    eb[(nl + 1) * 132 + m + 8] = c[mf][nf][3];
                }
        }
        __syncthreads();
        {
            int nl = t >> 4;
            int mm = (t & 15) * 8;
            int ng2 = nc * 32 + nl;
            float bias = pb[ng2];
            float* orow = out + (size_t)(bq * CH + ng2) * HWSZ + hw0;
#pragma unroll
            for (int j = 0; j < 2; ++j) {
                float4 v = *(float4*)&eb[nl * 132 + mm + j * 4];
                v.x += bias; v.y += bias; v.z += bias; v.w += bias;
                *(float4*)&orow[mm + j * 4] = v;
            }
        }
        __syncthreads();
    }
}

// ------------------------------------------------------------------
extern "C" void kernel_launch(void* const* d_in, const int* in_sizes, int n_in,
                              void* d_out, int out_size)
{
    const float* x      = (const float*)d_in[0];
    const float* qkv_w  = (const float*)d_in[1];
    const float* qkv_b  = (const float*)d_in[2];
    const float* rpb    = (const float*)d_in[3];
    const float* proj_w = (const float*)d_in[4];
    const float* proj_b = (const float*)d_in[5];
    float* out = (float*)d_out;

    cudaFuncSetAttribute(qkvdot_kernel,
                         cudaFuncAttributeMaxDynamicSharedMemorySize, QSM);
    cudaFuncSetAttribute(proj_kernel,
                         cudaFuncAttributeMaxDynamicSharedMemorySize, PSM);

    split_w_kernel<<<(3 * CH * CH + CH * CH) / 1024, 256>>>(qkv_w, proj_w);
    qkvdot_kernel<<<784, 512, QSM>>>(x, qkv_b);
    attn_kernel<<<dim3(7, 7, 32), 128>>>(rpb);
    proj_kernel<<<784, 512, PSM>>>(proj_b, out);
}

// round 14
// speedup vs baseline: 1.7429x; 1.0594x over previous
#include <cuda_runtime.h>
#include <cuda_bf16.h>

#define BATCH 8
#define CH    128
#define HH    112
#define WW    112
#define HWSZ  12544     // 112*112
#define NH    4
#define HD    32
#define KS    7
#define KK2   49
#define SCALE 0.17677669529663687f   // 32^-0.5

// Persistent scratch (static device allocations).
static __device__ __align__(16) __nv_bfloat16 g_wqh[3*CH*CH];        // qkv_w hi, [n][k]
static __device__ __align__(16) __nv_bfloat16 g_wql[3*CH*CH];
static __device__ __align__(16) __nv_bfloat16 g_pwh[CH*CH];          // proj_w hi
static __device__ __align__(16) __nv_bfloat16 g_pwl[CH*CH];
static __device__ __align__(16) float g_v  [BATCH*NH*HWSZ*HD];       // (b,h,p,d)
static __device__ __align__(16) float g_dot[BATCH*NH*HWSZ];          // (b,h,p)
// att hi/lo in HEAD-BLOCKED layout (b,h,p,d): attn stores coalesce.
static __device__ __align__(16) __nv_bfloat16 g_ath[BATCH*NH*HWSZ*HD];
static __device__ __align__(16) __nv_bfloat16 g_atl[BATCH*NH*HWSZ*HD];

// ---------------- helpers ----------------------------------------

__device__ __forceinline__ unsigned bfpack(__nv_bfloat16 a, __nv_bfloat16 b) {
    return (unsigned)__bfloat16_as_ushort(a) | ((unsigned)__bfloat16_as_ushort(b) << 16);
}

__device__ __forceinline__ void split4(float4 v, uint2& hi, uint2& lo) {
    __nv_bfloat16 hx = __float2bfloat16(v.x);
    __nv_bfloat16 hy = __float2bfloat16(v.y);
    __nv_bfloat16 hz = __float2bfloat16(v.z);
    __nv_bfloat16 hw = __float2bfloat16(v.w);
    __nv_bfloat16 lx = __float2bfloat16(v.x - __bfloat162float(hx));
    __nv_bfloat16 ly = __float2bfloat16(v.y - __bfloat162float(hy));
    __nv_bfloat16 lz = __float2bfloat16(v.z - __bfloat162float(hz));
    __nv_bfloat16 lw = __float2bfloat16(v.w - __bfloat162float(hw));
    hi.x = bfpack(hx, hy); hi.y = bfpack(hz, hw);
    lo.x = bfpack(lx, ly); lo.y = bfpack(lz, lw);
}

__device__ __forceinline__ void ldsm4(unsigned* r, unsigned addr) {
    asm volatile("ldmatrix.sync.aligned.m8n8.x4.shared.b16 {%0,%1,%2,%3}, [%4];"
                 : "=r"(r[0]), "=r"(r[1]), "=r"(r[2]), "=r"(r[3]) : "r"(addr));
}
__device__ __forceinline__ void ldsm4t(unsigned* r, unsigned addr) {
    asm volatile("ldmatrix.sync.aligned.m8n8.x4.trans.shared.b16 {%0,%1,%2,%3}, [%4];"
                 : "=r"(r[0]), "=r"(r[1]), "=r"(r[2]), "=r"(r[3]) : "r"(addr));
}
__device__ __forceinline__ void mma16816(float* c, const unsigned* a, const unsigned* b) {
    asm volatile(
        "mma.sync.aligned.m16n8k16.row.col.f32.bf16.bf16.f32 "
        "{%0,%1,%2,%3}, {%4,%5,%6,%7}, {%8,%9}, {%0,%1,%2,%3};"
        : "+f"(c[0]), "+f"(c[1]), "+f"(c[2]), "+f"(c[3])
        : "r"(a[0]), "r"(a[1]), "r"(a[2]), "r"(a[3]), "r"(b[0]), "r"(b[1]));
}

__device__ __forceinline__ void cpa16(unsigned dst, const void* src) {
    asm volatile("cp.async.cg.shared.global [%0], [%1], 16;" :: "r"(dst), "l"(src));
}
__device__ __forceinline__ void cpcommit() { asm volatile("cp.async.commit_group;"); }
__device__ __forceinline__ void cpwait1()  { asm volatile("cp.async.wait_group 1;"); }
__device__ __forceinline__ void cpwait0()  { asm volatile("cp.async.wait_group 0;"); }

// ------------------------------------------------------------------
// Pre-split kernel: weights fp32 -> bf16 hi/lo (tiny)
// ------------------------------------------------------------------
__global__ __launch_bounds__(256) void split_w_kernel(
    const float* __restrict__ qw, const float* __restrict__ pw)
{
    int i = (blockIdx.x * 256 + threadIdx.x) * 4;
    uint2 hi, lo;
    if (i < 3 * CH * CH) {
        float4 v = *(const float4*)&qw[i];
        split4(v, hi, lo);
        *(uint2*)&g_wqh[i] = hi;
        *(uint2*)&g_wql[i] = lo;
    } else {
        int j = i - 3 * CH * CH;
        float4 v = *(const float4*)&pw[j];
        split4(v, hi, lo);
        *(uint2*)&g_pwh[j] = hi;
        *(uint2*)&g_pwl[j] = lo;
    }
}

// ------------------------------------------------------------------
// Kernel 1: fused QKV GEMM + q.k dot. bf16 3-term split.
// BK=64, 6 phases, 3-buffer cp.async ring. (byte-identical to R12)
// ------------------------------------------------------------------
#define QA_H 0
#define QA_L 34816
#define QB0  69632
#define QBUF 36864
#define QSM  180224    // 69632 + 3*36864

__device__ __forceinline__ void qkv_issueB(unsigned sb, int t, int p)
{
    const int nt = p >> 1, ktH = p & 1, buf = p % 3;
    const int nrow = t >> 2, c4 = t & 3;
    unsigned bd = sb + QB0 + buf * QBUF + nrow * 144 + c4 * 32;
    size_t off = (size_t)(nt * 128 + nrow) * CH + ktH * 64 + c4 * 16;
    cpa16(bd,              g_wqh + off);
    cpa16(bd + 16,         g_wqh + off + 8);
    cpa16(bd + 18432,      g_wql + off);
    cpa16(bd + 18432 + 16, g_wql + off + 8);
}

__global__ __launch_bounds__(512) void qkvdot_kernel(
    const float* __restrict__ x, const float* __restrict__ bias)
{
    extern __shared__ __align__(16) char sm[];
    const unsigned sb = (unsigned)__cvta_generic_to_shared(sm);

    const int mtile = blockIdx.x;            // 0..783
    const int b     = mtile / 98;
    const int hw0   = (mtile - b * 98) * 128;
    const int t     = threadIdx.x;
    const int l     = t & 31, w = t >> 5;
    const int wm    = w >> 2, wn = w & 3;
    const int g     = l >> 3, i = l & 7;

    // ---- prologue: B(0), B(1) via cp.async; A fp32 load + split ----
    {
        qkv_issueB(sb, t, 0);
        cpcommit();
        qkv_issueB(sb, t, 1);
        cpcommit();

        const float* xb = x + (size_t)b * (CH * HWSZ) + hw0;
        const int m4 = (t & 31) * 4;
        const int kr = t >> 5;               // 0..15
        float4 av[8];
#pragma unroll
        for (int j = 0; j < 8; ++j)
            av[j] = *(const float4*)(xb + (size_t)(kr + j * 16) * HWSZ + m4);
#pragma unroll
        for (int j = 0; j < 8; ++j) {
            uint2 hi, lo;
            split4(av[j], hi, lo);
            unsigned ad = sb + QA_H + (kr + j * 16) * 272 + m4 * 2;
            *(uint2*)__cvta_shared_to_generic(ad) = hi;
            *(uint2*)__cvta_shared_to_generic(ad + (QA_L - QA_H)) = lo;
        }
        cpwait1();
        __syncthreads();
    }

    float c[2][4][4];
    float qreg[2][4][4];
#pragma unroll
    for (int mf = 0; mf < 2; ++mf)
#pragma unroll
        for (int nf = 0; nf < 4; ++nf)
#pragma unroll
            for (int r2 = 0; r2 < 4; ++r2) c[mf][nf][r2] = 0.f;

    for (int p = 0; p < 6; ++p) {
        const int nt = p >> 1, ktH = p & 1, buf = p % 3;

        if (p < 4) { qkv_issueB(sb, t, p + 2); cpcommit(); }

        const unsigned Bb = sb + QB0 + buf * QBUF;
#pragma unroll
        for (int kb = 0; kb < 64; kb += 16) {
            unsigned ah[2][4], al_[2][4], bh[4][2], bl[4][2];
#pragma unroll
            for (int mf = 0; mf < 2; ++mf) {
                int row  = ktH * 64 + kb + i + ((g >> 1) << 3);
                int mcol = wm * 32 + mf * 16 + ((g & 1) << 3);
                unsigned ad = sb + QA_H + row * 272 + mcol * 2;
                ldsm4t(ah[mf], ad);
                ldsm4t(al_[mf], ad + (QA_L - QA_H));
            }
#pragma unroll
            for (int ng = 0; ng < 2; ++ng) {
                int nrow = wn * 32 + ng * 16 + ((g >> 1) << 3) + i;
                unsigned bd = Bb + nrow * 144 + kb * 2 + ((g & 1) << 4);
                unsigned r[4];
                ldsm4(r, bd);
                bh[ng * 2][0] = r[0]; bh[ng * 2][1] = r[1];
                bh[ng * 2 + 1][0] = r[2]; bh[ng * 2 + 1][1] = r[3];
                ldsm4(r, bd + 18432);
                bl[ng * 2][0] = r[0]; bl[ng * 2][1] = r[1];
                bl[ng * 2 + 1][0] = r[2]; bl[ng * 2 + 1][1] = r[3];
            }
#pragma unroll
            for (int mf = 0; mf < 2; ++mf)
#pragma unroll
                for (int nf = 0; nf < 4; ++nf) {
                    mma16816(c[mf][nf], ah[mf], bh[nf]);
                    mma16816(c[mf][nf], ah[mf], bl[nf]);
                    mma16816(c[mf][nf], al_[mf], bh[nf]);
                }
        }

        if (ktH == 1) {
            if (nt == 0) {
#pragma unroll
                for (int mf = 0; mf < 2; ++mf)
#pragma unroll
                    for (int nf = 0; nf < 4; ++nf) {
                        int n = wn * 32 + nf * 8 + (l & 3) * 2;
                        float b0 = bias[n], b1 = bias[n + 1];
                        qreg[mf][nf][0] = c[mf][nf][0] + b0;
                        qreg[mf][nf][1] = c[mf][nf][1] + b1;
                        qreg[mf][nf][2] = c[mf][nf][2] + b0;
                        qreg[mf][nf][3] = c[mf][nf][3] + b1;
                    }
            } else if (nt == 1) {
#pragma unroll
                for (int mf = 0; mf < 2; ++mf) {
                    float s0 = 0.f, s1 = 0.f;
                    int m = wm * 32 + mf * 16 + (l >> 2);
#pragma unroll
                    for (int nf = 0; nf < 4; ++nf) {
                        int n = wn * 32 + nf * 8 + (l & 3) * 2;
                        float b0 = bias[128 + n], b1 = bias[128 + n + 1];
                        s0 += qreg[mf][nf][0] * (c[mf][nf][0] + b0)
                            + qreg[mf][nf][1] * (c[mf][nf][1] + b1);
                        s1 += qreg[mf][nf][2] * (c[mf][nf][2] + b0)
                            + qreg[mf][nf][3] * (c[mf][nf][3] + b1);
                    }
                    s0 += __shfl_xor_sync(0xffffffffu, s0, 1);
                    s0 += __shfl_xor_sync(0xffffffffu, s0, 2);
                    s1 += __shfl_xor_sync(0xffffffffu, s1, 1);
                    s1 += __shfl_xor_sync(0xffffffffu, s1, 2);
                    if ((l & 3) == 0) {
                        size_t base = (size_t)(b * NH + wn) * HWSZ + hw0;
                        g_dot[base + m]     = s0 * SCALE;
                        g_dot[base + m + 8] = s1 * SCALE;
                    }
                }
            } else {
#pragma unroll
                for (int mf = 0; mf < 2; ++mf)
#pragma unroll
                    for (int nf = 0; nf < 4; ++nf) {
                        int n = wn * 32 + nf * 8 + (l & 3) * 2;
                        int m = wm * 32 + mf * 16 + (l >> 2);
                        float b0 = bias[256 + n], b1 = bias[256 + n + 1];
                        int d = n & 31;
                        float* hb = g_v + ((size_t)(b * NH + wn) * HWSZ + hw0) * HD + d;
                        *(float2*)&hb[(size_t)m * HD] =
                            make_float2(c[mf][nf][0] + b0, c[mf][nf][1] + b1);
                        *(float2*)&hb[(size_t)(m + 8) * HD] =
                            make_float2(c[mf][nf][2] + b0, c[mf][nf][3] + b1);
                    }
            }
#pragma unroll
            for (int mf = 0; mf < 2; ++mf)
#pragma unroll
                for (int nf = 0; nf < 4; ++nf)
#pragma unroll
                    for (int r2 = 0; r2 < 4; ++r2) c[mf][nf][r2] = 0.f;
        }

        if (p < 4)       cpwait1();
        else if (p == 4) cpwait0();
        __syncthreads();
    }
}

// ------------------------------------------------------------------
// Kernel 2: neighborhood attention (circular), vertical 2-px strip.
// (byte-identical to R11/R12 — frozen at its win)
// ------------------------------------------------------------------
__global__ __launch_bounds__(128) void attn_kernel(const float* __restrict__ rpb)
{
    __shared__ __align__(16) float ds[22 * 24];
    __shared__ __align__(16) float rs[KK2];
    __shared__ __align__(16) float vs[484 * 20];

    const int bh = blockIdx.z;        // b*4 + h
    const int h  = bh & 3;
    const int b  = bh >> 2;
    const int y0 = blockIdx.y * 16;
    const int x0 = blockIdx.x * 16;
    const int tid = threadIdx.x;

    for (int idx = tid; idx < 484; idx += 128) {
        int r  = idx / 22, cc = idx - r * 22;
        int gy = y0 + r;  if (gy >= HH) gy -= HH;
        int gx = x0 + cc; if (gx >= WW) gx -= WW;
        ds[r * 24 + cc] = g_dot[(size_t)bh * HWSZ + gy * WW + gx];
    }
    if (tid < KK2) rs[tid] = rpb[h * KK2 + tid];

    const float* vbase = g_v + (size_t)bh * (HWSZ * HD);

    for (int idx = tid; idx < 484 * 4; idx += 128) {
        int pix = idx >> 2, gg = idx & 3;
        int r  = pix / 22, cc = pix - r * 22;
        int gy = y0 + r;  if (gy >= HH) gy -= HH;
        int gx = x0 + cc; if (gx >= WW) gx -= WW;
        *(float4*)&vs[pix * 20 + gg * 4] =
            *(const float4*)&vbase[(size_t)(gy * WW + gx) * HD + gg * 4];
    }
    __syncthreads();

    const int ty2 = tid >> 4;          // 0..7 -> rows 2*ty2, 2*ty2+1
    const int tx  = tid & 15;

    float wgt[2][KK2];
#pragma unroll
    for (int px = 0; px < 2; ++px) {
        float mx = -1e30f;
#pragma unroll
        for (int i = 0; i < 7; ++i)
#pragma unroll
            for (int j = 0; j < 7; ++j) {
                float val = ds[(2 * ty2 + px + i) * 24 + tx + j] + rs[i * 7 + j];
                wgt[px][i * 7 + j] = val;
                mx = fmaxf(mx, val);
            }
        float sum = 0.f;
#pragma unroll
        for (int n = 0; n < KK2; ++n) { wgt[px][n] = __expf(wgt[px][n] - mx); sum += wgt[px][n]; }
        float inv = 1.f / sum;
#pragma unroll
        for (int n = 0; n < KK2; ++n) wgt[px][n] *= inv;
    }

    const int p0 = (y0 + 2 * ty2) * WW + (x0 + tx);
    const size_t ob0 = ((size_t)(b * NH + h) * HWSZ + p0) * HD;
    const size_t ob1 = ob0 + (size_t)WW * HD;

#pragma unroll
    for (int half = 0; half < 2; ++half) {
        if (half == 1) {
            __syncthreads();
            for (int idx = tid; idx < 484 * 4; idx += 128) {
                int pix = idx >> 2, gg = idx & 3;
                int r  = pix / 22, cc = pix - r * 22;
                int gy = y0 + r;  if (gy >= HH) gy -= HH;
                int gx = x0 + cc; if (gx >= WW) gx -= WW;
                *(float4*)&vs[pix * 20 + gg * 4] =
                    *(const float4*)&vbase[(size_t)(gy * WW + gx) * HD + 16 + gg * 4];
            }
            __syncthreads();
        }

        float4 acc0[4], acc1[4];
#pragma unroll
        for (int gg = 0; gg < 4; ++gg) {
            acc0[gg] = make_float4(0.f, 0.f, 0.f, 0.f);
            acc1[gg] = make_float4(0.f, 0.f, 0.f, 0.f);
        }
#pragma unroll
        for (int i = 0; i < 8; ++i)
#pragma unroll
            for (int j = 0; j < 7; ++j) {
                int pix = (2 * ty2 + i) * 22 + (tx + j);
                float w0 = (i < 7) ? wgt[0][i * 7 + j] : 0.f;
                float w1 = (i >= 1) ? wgt[1][(i - 1) * 7 + j] : 0.f;
#pragma unroll
                for (int gg = 0; gg < 4; ++gg) {
                    float4 vv = *(const float4*)&vs[pix * 20 + gg * 4];
                    if (i < 7) {
                        acc0[gg].x = fmaf(w0, vv.x, acc0[gg].x);
                        acc0[gg].y = fmaf(w0, vv.y, acc0[gg].y);
                        acc0[gg].z = fmaf(w0, vv.z, acc0[gg].z);
                        acc0[gg].w = fmaf(w0, vv.w, acc0[gg].w);
                    }
                    if (i >= 1) {
                        acc1[gg].x = fmaf(w1, vv.x, acc1[gg].x);
                        acc1[gg].y = fmaf(w1, vv.y, acc1[gg].y);
                        acc1[gg].z = fmaf(w1, vv.z, acc1[gg].z);
                        acc1[gg].w = fmaf(w1, vv.w, acc1[gg].w);
                    }
                }
            }

#pragma unroll
        for (int px = 0; px < 2; ++px) {
            float4* acc = px ? acc1 : acc0;
            unsigned hi_u[8], lo_u[8];
#pragma unroll
            for (int gg = 0; gg < 4; ++gg) {
                float f[4] = { acc[gg].x, acc[gg].y, acc[gg].z, acc[gg].w };
#pragma unroll
                for (int e = 0; e < 2; ++e) {
                    float f0 = f[e * 2], f1 = f[e * 2 + 1];
                    __nv_bfloat16 h0 = __float2bfloat16(f0);
                    __nv_bfloat16 h1 = __float2bfloat16(f1);
                    __nv_bfloat16 l0 = __float2bfloat16(f0 - __bfloat162float(h0));
                    __nv_bfloat16 l1 = __float2bfloat16(f1 - __bfloat162float(h1));
                    hi_u[gg * 2 + e] = bfpack(h0, h1);
                    lo_u[gg * 2 + e] = bfpack(l0, l1);
                }
            }
            size_t ob = (px ? ob1 : ob0) + half * 16;
            *(uint4*)&g_ath[ob]     = make_uint4(hi_u[0], hi_u[1], hi_u[2], hi_u[3]);
            *(uint4*)&g_ath[ob + 8] = make_uint4(hi_u[4], hi_u[5], hi_u[6], hi_u[7]);
            *(uint4*)&g_atl[ob]     = make_uint4(lo_u[0], lo_u[1], lo_u[2], lo_u[3]);
            *(uint4*)&g_atl[ob + 8] = make_uint4(lo_u[4], lo_u[5], lo_u[6], lo_u[7]);
        }
    }
}

// ------------------------------------------------------------------
// Kernel 3: proj GEMM. A+B streamed per kt (ring-3, R12 mainloop).
// NEW: direct strided-STG epilogue (no smem transpose, no barriers):
// lanes sharing l&3 store 8 consecutive m -> 32B runs, sector-
// efficient; removes 8 __syncthreads + STS/LDS round trip.
// ------------------------------------------------------------------
#define PBUF 40960
#define PSM  122880    // 3*40960

__device__ __forceinline__ void proj_issue(unsigned sb, int t, int bq, int hw0, int kt)
{
    const unsigned base = sb + (kt % 3) * PBUF;
    const int mrow = t >> 2, c4 = t & 3;
    unsigned ad = base + mrow * 80 + c4 * 16;
    size_t aoff = ((size_t)(bq * NH + kt) * HWSZ + hw0 + mrow) * HD + c4 * 8;
    cpa16(ad,         g_ath + aoff);
    cpa16(ad + 10240, g_atl + aoff);
    unsigned bd = base + 20480 + mrow * 80 + c4 * 16;
    size_t boff = (size_t)mrow * CH + kt * 32 + c4 * 8;
    cpa16(bd,         g_pwh + boff);
    cpa16(bd + 10240, g_pwl + boff);
}

__global__ __launch_bounds__(512) void proj_kernel(
    const float* __restrict__ pb, float* __restrict__ out)
{
    extern __shared__ __align__(16) char sm[];
    const unsigned sb = (unsigned)__cvta_generic_to_shared(sm);

    const int mtile = blockIdx.x;
    const int bq    = mtile / 98;
    const int hw0   = (mtile - bq * 98) * 128;
    const int t     = threadIdx.x;
    const int l     = t & 31, w = t >> 5;
    const int wm    = w >> 2, wn = w & 3;
    const int g     = l >> 3, i = l & 7;

    {
        proj_issue(sb, t, bq, hw0, 0);
        cpcommit();
        proj_issue(sb, t, bq, hw0, 1);
        cpcommit();
        cpwait1();
        __syncthreads();
    }

    float c[2][4][4];
#pragma unroll
    for (int mf = 0; mf < 2; ++mf)
#pragma unroll
        for (int nf = 0; nf < 4; ++nf)
#pragma unroll
            for (int r2 = 0; r2 < 4; ++r2) c[mf][nf][r2] = 0.f;

    for (int kt = 0; kt < 4; ++kt) {
        const unsigned Cb = sb + (kt % 3) * PBUF;
        if (kt < 2) { proj_issue(sb, t, bq, hw0, kt + 2); cpcommit(); }

#pragma unroll
        for (int kb = 0; kb < 32; kb += 16) {
            unsigned ah[2][4], al_[2][4], bh[4][2], bl[4][2];
#pragma unroll
            for (int mf = 0; mf < 2; ++mf) {
                int mrow = wm * 32 + mf * 16 + ((g & 1) << 3) + i;
                unsigned ad = Cb + mrow * 80 + kb * 2 + ((g >> 1) << 4);
                ldsm4(ah[mf], ad);
                ldsm4(al_[mf], ad + 10240);
            }
#pragma unroll
            for (int ng = 0; ng < 2; ++ng) {
                int nrow = wn * 32 + ng * 16 + ((g >> 1) << 3) + i;
                unsigned bd = Cb + 20480 + nrow * 80 + kb * 2 + ((g & 1) << 4);
                unsigned r[4];
                ldsm4(r, bd);
                bh[ng * 2][0] = r[0]; bh[ng * 2][1] = r[1];
                bh[ng * 2 + 1][0] = r[2]; bh[ng * 2 + 1][1] = r[3];
                ldsm4(r, bd + 10240);
                bl[ng * 2][0] = r[0]; bl[ng * 2][1] = r[1];
                bl[ng * 2 + 1][0] = r[2]; bl[ng * 2 + 1][1] = r[3];
            }
#pragma unroll
            for (int mf = 0; mf < 2; ++mf)
#pragma unroll
                for (int nf = 0; nf < 4; ++nf) {
                    mma16816(c[mf][nf], ah[mf], bh[nf]);
                    mma16816(c[mf][nf], ah[mf], bl[nf]);
                    mma16816(c[mf][nf], al_[mf], bh[nf]);
                }
        }
        if (kt < 2)       cpwait1();
        else if (kt == 2) cpwait0();
        __syncthreads();
    }

    // ---- direct STG epilogue: out[bq, n, hw0 + m] = c + pb[n] ----
#pragma unroll
    for (int mf = 0; mf < 2; ++mf)
#pragma unroll
        for (int nf = 0; nf < 4; ++nf) {
            int n = wn * 32 + nf * 8 + (l & 3) * 2;
            int m = wm * 32 + mf * 16 + (l >> 2);
            float b0 = pb[n], b1 = pb[n + 1];
            float* r0 = out + (size_t)(bq * CH + n) * HWSZ + hw0;
            float* r1 = out + (size_t)(bq * CH + n + 1) * HWSZ + hw0;
            r0[m]     = c[mf][nf][0] + b0;
            r1[m]     = c[mf][nf][1] + b1;
            r0[m + 8] = c[mf][nf][2] + b0;
            r1[m + 8] = c[mf][nf][3] + b1;
        }
}

// ------------------------------------------------------------------
extern "C" void kernel_launch(void* const* d_in, const int* in_sizes, int n_in,
                              void* d_out, int out_size)
{
    const float* x      = (const float*)d_in[0];
    const float* qkv_w  = (const float*)d_in[1];
    const float* qkv_b  = (const float*)d_in[2];
    const float* rpb    = (const float*)d_in[3];
    const float* proj_w = (const float*)d_in[4];
    const float* proj_b = (const float*)d_in[5];
    float* out = (float*)d_out;

    cudaFuncSetAttribute(qkvdot_kernel,
                         cudaFuncAttributeMaxDynamicSharedMemorySize, QSM);
    cudaFuncSetAttribute(proj_kernel,
                         cudaFuncAttributeMaxDynamicSharedMemorySize, PSM);

    split_w_kernel<<<(3 * CH * CH + CH * CH) / 1024, 256>>>(qkv_w, proj_w);
    qkvdot_kernel<<<784, 512, QSM>>>(x, qkv_b);
    attn_kernel<<<dim3(7, 7, 32), 128>>>(rpb);
    proj_kernel<<<784, 512, PSM>>>(proj_b, out);
}